// round 4
// baseline (speedup 1.0000x reference)
#include <cuda_runtime.h>
#include <math.h>
#include <stdint.h>

#define SEQ 2048
#define NH 16
#define DQK 192

// ---------------- scratch (no allocations allowed) ----------------
__device__ __align__(16) float g_q1[SEQ * 1536];
__device__ __align__(16) float g_q [SEQ * 3072];
__device__ __align__(16) float g_ckv[SEQ * 512];
__device__ __align__(16) float g_k [SEQ * 3072];
__device__ __align__(16) float g_v [SEQ * 2048];
__device__ __align__(16) float g_attn[SEQ * 2048];

// round fp32 -> tf32 (RNA), keep as float bit-pattern
__device__ __forceinline__ float tf32r(float x) {
    unsigned u;
    asm("cvt.rna.tf32.f32 %0, %1;" : "=r"(u) : "f"(x));
    return __uint_as_float(u);
}
__device__ __forceinline__ unsigned fb(float x) { return __float_as_uint(x); }

__device__ __forceinline__ void mma_tf32(float* c, const unsigned* a, const unsigned* b) {
    asm("mma.sync.aligned.m16n8k8.row.col.f32.tf32.tf32.f32 "
        "{%0,%1,%2,%3}, {%4,%5,%6,%7}, {%8,%9}, {%0,%1,%2,%3};"
        : "+f"(c[0]), "+f"(c[1]), "+f"(c[2]), "+f"(c[3])
        : "r"(a[0]), "r"(a[1]), "r"(a[2]), "r"(a[3]), "r"(b[0]), "r"(b[1]));
}

__device__ __forceinline__ void cp16(uint32_t dst, const float* src) {
    asm volatile("cp.async.cg.shared.global [%0], [%1], 16;"
                 :: "r"(dst), "l"(__cvta_generic_to_global(src)));
}

// ---------------- tf32 tensor-core GEMM (projections) ----------------
// C[m,n] = scale * sum_k A[m,k] * B[k,n]; optional tf32 rounding of output.
template <bool ROUND>
__global__ __launch_bounds__(256, 2) void gemm_tf32(
    const float* __restrict__ A, const float* __restrict__ B,
    float* __restrict__ C, int K, int lda, int ldb, int ldc)
{
    __shared__ float As[2][16][132];   // [k][m]
    __shared__ float Bs[2][16][132];   // [k][n]

    const int t = threadIdx.x;
    const int m0 = blockIdx.y * 128;
    const int n0 = blockIdx.x * 128;

    const int am = t >> 1;
    const int ak = (t & 1) * 8;
    const int bk = t >> 4;
    const int bn = (t & 15) * 8;

    const int lane = t & 31;
    const int warp = t >> 5;
    const int wm = (warp >> 2) * 64;
    const int wn = (warp & 3) * 32;
    const int qk = lane & 3;
    const int qr = lane >> 2;

    float acc[4][4][4] = {};
    float4 ra0, ra1, rb0, rb1;

    {
        const float* pa = A + (size_t)(m0 + am) * lda + ak;
        ra0 = *(const float4*)pa; ra1 = *(const float4*)(pa + 4);
        const float* pb = B + (size_t)bk * ldb + n0 + bn;
        rb0 = *(const float4*)pb; rb1 = *(const float4*)(pb + 4);
        As[0][ak + 0][am] = tf32r(ra0.x); As[0][ak + 1][am] = tf32r(ra0.y);
        As[0][ak + 2][am] = tf32r(ra0.z); As[0][ak + 3][am] = tf32r(ra0.w);
        As[0][ak + 4][am] = tf32r(ra1.x); As[0][ak + 5][am] = tf32r(ra1.y);
        As[0][ak + 6][am] = tf32r(ra1.z); As[0][ak + 7][am] = tf32r(ra1.w);
        Bs[0][bk][bn + 0] = tf32r(rb0.x); Bs[0][bk][bn + 1] = tf32r(rb0.y);
        Bs[0][bk][bn + 2] = tf32r(rb0.z); Bs[0][bk][bn + 3] = tf32r(rb0.w);
        Bs[0][bk][bn + 4] = tf32r(rb1.x); Bs[0][bk][bn + 5] = tf32r(rb1.y);
        Bs[0][bk][bn + 6] = tf32r(rb1.z); Bs[0][bk][bn + 7] = tf32r(rb1.w);
    }
    __syncthreads();

    int buf = 0;
    for (int kt = 0; kt < K; kt += 16) {
        const bool more = (kt + 16) < K;
        if (more) {
            const float* pa = A + (size_t)(m0 + am) * lda + kt + 16 + ak;
            ra0 = *(const float4*)pa; ra1 = *(const float4*)(pa + 4);
            const float* pb = B + (size_t)(kt + 16 + bk) * ldb + n0 + bn;
            rb0 = *(const float4*)pb; rb1 = *(const float4*)(pb + 4);
        }

        #pragma unroll
        for (int k8 = 0; k8 < 16; k8 += 8) {
            unsigned af[4][4], bfr[4][2];
            #pragma unroll
            for (int mi = 0; mi < 4; mi++) {
                const int m = wm + mi * 16 + qr;
                af[mi][0] = fb(As[buf][k8 + qk][m]);
                af[mi][1] = fb(As[buf][k8 + qk][m + 8]);
                af[mi][2] = fb(As[buf][k8 + qk + 4][m]);
                af[mi][3] = fb(As[buf][k8 + qk + 4][m + 8]);
            }
            #pragma unroll
            for (int ni = 0; ni < 4; ni++) {
                const int n = wn + ni * 8 + qr;
                bfr[ni][0] = fb(Bs[buf][k8 + qk][n]);
                bfr[ni][1] = fb(Bs[buf][k8 + qk + 4][n]);
            }
            #pragma unroll
            for (int mi = 0; mi < 4; mi++)
                #pragma unroll
                for (int ni = 0; ni < 4; ni++)
                    mma_tf32(acc[mi][ni], af[mi], bfr[ni]);
        }

        if (more) {
            const int nb = buf ^ 1;
            As[nb][ak + 0][am] = tf32r(ra0.x); As[nb][ak + 1][am] = tf32r(ra0.y);
            As[nb][ak + 2][am] = tf32r(ra0.z); As[nb][ak + 3][am] = tf32r(ra0.w);
            As[nb][ak + 4][am] = tf32r(ra1.x); As[nb][ak + 5][am] = tf32r(ra1.y);
            As[nb][ak + 6][am] = tf32r(ra1.z); As[nb][ak + 7][am] = tf32r(ra1.w);
            Bs[nb][bk][bn + 0] = tf32r(rb0.x); Bs[nb][bk][bn + 1] = tf32r(rb0.y);
            Bs[nb][bk][bn + 2] = tf32r(rb0.z); Bs[nb][bk][bn + 3] = tf32r(rb0.w);
            Bs[nb][bk][bn + 4] = tf32r(rb1.x); Bs[nb][bk][bn + 5] = tf32r(rb1.y);
            Bs[nb][bk][bn + 6] = tf32r(rb1.z); Bs[nb][bk][bn + 7] = tf32r(rb1.w);
            __syncthreads();
            buf ^= 1;
        }
    }

    #pragma unroll
    for (int mi = 0; mi < 4; mi++) {
        #pragma unroll
        for (int ni = 0; ni < 4; ni++) {
            const int m = m0 + wm + mi * 16 + qr;
            const int n = n0 + wn + ni * 8 + 2 * qk;
            float2 v0, v1;
            if (ROUND) {
                v0.x = tf32r(acc[mi][ni][0]); v0.y = tf32r(acc[mi][ni][1]);
                v1.x = tf32r(acc[mi][ni][2]); v1.y = tf32r(acc[mi][ni][3]);
            } else {
                v0.x = acc[mi][ni][0]; v0.y = acc[mi][ni][1];
                v1.x = acc[mi][ni][2]; v1.y = acc[mi][ni][3];
            }
            *(float2*)(C + (size_t)m * ldc + n)       = v0;
            *(float2*)(C + (size_t)(m + 8) * ldc + n) = v1;
        }
    }
}

// ---------------- RoPE (in place, rounds output to tf32) ----------------
__global__ void rope_kernel(float* __restrict__ X)
{
    int idx = blockIdx.x * blockDim.x + threadIdx.x;
    int j = idx & 31;
    int h = (idx >> 5) & (NH - 1);
    int t = idx >> 9;
    float* p = X + (size_t)t * 3072 + h * DQK + 128;
    float inv = powf(10000.0f, -(float)j / 32.0f);
    float ang = (float)t * inv;
    float s, c;
    sincosf(ang, &s, &c);
    float x1 = p[j], x2 = p[j + 32];
    p[j]      = tf32r(x1 * c - x2 * s);
    p[j + 32] = tf32r(x2 * c + x1 * s);
}

// ---------------- fused causal flash attention (v2) ----------------
// Per CTA: one head, 128 Q rows. Q fragments in registers.
// K/V double-buffered in smem via cp.async. 8 warps x 16 rows.
#define LDK 196
#define LDV 136
#define LDP 68
#define KBUF (64 * LDK)            // 12544 floats
#define VBUF (64 * LDV)            // 8704 floats
#define OFF_K0 0
#define OFF_K1 KBUF
#define OFF_V0 (2 * KBUF)          // 25088 (Q stage = 128*196 = 25088, aliases K0+K1)
#define OFF_V1 (OFF_V0 + VBUF)
#define OFF_P  (OFF_V1 + VBUF)
#define FLASH_SMEM ((OFF_P + 128 * LDP) * 4)   // 204800 bytes

__device__ __forceinline__ void load_kv(
    uint32_t sbase, int buf, int jt, int h, int tid,
    const float* __restrict__ Kg, const float* __restrict__ Vg)
{
    uint32_t kdst = sbase + (buf ? OFF_K1 : OFF_K0) * 4;
    const float* ksrc = Kg + (size_t)(jt * 64) * 3072 + h * DQK;
    #pragma unroll
    for (int i = 0; i < 12; i++) {
        int idx = tid + i * 256;            // 3072 chunks of 16B (48/row)
        int r = idx / 48, c = idx % 48;
        cp16(kdst + (r * LDK + c * 4) * 4, ksrc + (size_t)r * 3072 + c * 4);
    }
    uint32_t vdst = sbase + (buf ? OFF_V1 : OFF_V0) * 4;
    const float* vsrc = Vg + (size_t)(jt * 64) * 2048 + h * 128;
    #pragma unroll
    for (int i = 0; i < 8; i++) {
        int idx = tid + i * 256;            // 2048 chunks of 16B (32/row)
        int r = idx / 32, c = idx % 32;
        cp16(vdst + (r * LDV + c * 4) * 4, vsrc + (size_t)r * 2048 + c * 4);
    }
    asm volatile("cp.async.commit_group;");
}

__global__ __launch_bounds__(256, 1) void flash_attn(
    const float* __restrict__ Qg, const float* __restrict__ Kg,
    const float* __restrict__ Vg, float* __restrict__ Og)
{
    extern __shared__ float sm[];
    const uint32_t sbase = (uint32_t)__cvta_generic_to_shared(sm);

    const int h   = blockIdx.x;
    const int qt  = 15 - blockIdx.y;      // long CTAs first
    const int tid = threadIdx.x;
    const int lane = tid & 31;
    const int warp = tid >> 5;
    const int qr = lane >> 2;
    const int qk = lane & 3;
    const int wm = warp * 16;

    const float cs = 0.10411758f;         // log2(e)/sqrt(192)

    // ---- stage Q tile [128 x 192] into smem (region aliased with K bufs) ----
    {
        float* Qs = sm;
        #pragma unroll
        for (int i = 0; i < 24; i++) {
            int idx = tid + i * 256;       // 6144 float4 chunks (48/row)
            int r = idx / 48, c = idx % 48;
            float4 v4 = *(const float4*)(Qg + (size_t)(qt * 128 + r) * 3072 + h * DQK + c * 4);
            *(float4*)(Qs + r * LDK + c * 4) = v4;
        }
    }
    __syncthreads();

    // ---- extract Q fragments to registers (tf32-rounded) ----
    float qf[24][4];
    {
        const float* Qs = sm;
        const int r0 = (wm + qr) * LDK;
        const int r1 = (wm + qr + 8) * LDK;
        #pragma unroll
        for (int ks = 0; ks < 24; ks++) {
            qf[ks][0] = tf32r(Qs[r0 + ks * 8 + qk]);
            qf[ks][1] = tf32r(Qs[r1 + ks * 8 + qk]);
            qf[ks][2] = tf32r(Qs[r0 + ks * 8 + qk + 4]);
            qf[ks][3] = tf32r(Qs[r1 + ks * 8 + qk + 4]);
        }
    }
    __syncthreads();   // everyone done reading Q stage; K bufs may now be written

    const int njt = 2 * qt + 2;
    load_kv(sbase, 0, 0, h, tid, Kg, Vg);
    load_kv(sbase, 1, 1, h, tid, Kg, Vg);

    float o[16][4];
    #pragma unroll
    for (int i = 0; i < 16; i++)
        #pragma unroll
        for (int j = 0; j < 4; j++) o[i][j] = 0.f;
    float m0 = -1e30f, m1 = -1e30f, l0 = 0.f, l1 = 0.f;

    for (int jt = 0; jt < njt; jt++) {
        if (jt + 1 < njt) asm volatile("cp.async.wait_group 1;");
        else              asm volatile("cp.async.wait_group 0;");
        __syncthreads();   // stage jt visible to all

        const float* Ks = sm + (jt & 1 ? OFF_K1 : OFF_K0);
        const float* Vs = sm + (jt & 1 ? OFF_V1 : OFF_V0);
        float* Ps = sm + OFF_P;

        // ---- S = Q K^T : warp rows [wm, wm+16), cols [0,64) ----
        float s[8][4];
        #pragma unroll
        for (int i = 0; i < 8; i++)
            #pragma unroll
            for (int j = 0; j < 4; j++) s[i][j] = 0.f;

        #pragma unroll
        for (int ks = 0; ks < 24; ks++) {
            const unsigned* a = (const unsigned*)qf[ks];
            #pragma unroll
            for (int nf = 0; nf < 8; nf++) {
                unsigned b[2];
                const int row = (nf * 8 + qr) * LDK + ks * 8 + qk;
                b[0] = fb(Ks[row]);
                b[1] = fb(Ks[row + 4]);
                mma_tf32(s[nf], a, b);
            }
        }

        // ---- causal mask (only last two tiles cross the diagonal) ----
        const int rg0 = qt * 128 + wm + qr;
        if (jt >= 2 * qt) {
            #pragma unroll
            for (int nf = 0; nf < 8; nf++) {
                const int cg = jt * 64 + nf * 8 + 2 * qk;
                if (cg     > rg0)     s[nf][0] = -1e30f;
                if (cg + 1 > rg0)     s[nf][1] = -1e30f;
                if (cg     > rg0 + 8) s[nf][2] = -1e30f;
                if (cg + 1 > rg0 + 8) s[nf][3] = -1e30f;
            }
        }

        // ---- online softmax ----
        float mx0 = -1e30f, mx1 = -1e30f;
        #pragma unroll
        for (int nf = 0; nf < 8; nf++) {
            mx0 = fmaxf(mx0, fmaxf(s[nf][0], s[nf][1]));
            mx1 = fmaxf(mx1, fmaxf(s[nf][2], s[nf][3]));
        }
        mx0 = fmaxf(mx0, __shfl_xor_sync(0xffffffffu, mx0, 1));
        mx0 = fmaxf(mx0, __shfl_xor_sync(0xffffffffu, mx0, 2));
        mx1 = fmaxf(mx1, __shfl_xor_sync(0xffffffffu, mx1, 1));
        mx1 = fmaxf(mx1, __shfl_xor_sync(0xffffffffu, mx1, 2));

        const float mn0 = fmaxf(m0, mx0);
        const float mn1 = fmaxf(m1, mx1);
        const float al0 = exp2f((m0 - mn0) * cs);
        const float al1 = exp2f((m1 - mn1) * cs);
        m0 = mn0; m1 = mn1;

        float rs0 = 0.f, rs1 = 0.f;
        #pragma unroll
        for (int nf = 0; nf < 8; nf++) {
            s[nf][0] = exp2f((s[nf][0] - mn0) * cs);
            s[nf][1] = exp2f((s[nf][1] - mn0) * cs);
            s[nf][2] = exp2f((s[nf][2] - mn1) * cs);
            s[nf][3] = exp2f((s[nf][3] - mn1) * cs);
            rs0 += s[nf][0] + s[nf][1];
            rs1 += s[nf][2] + s[nf][3];
        }
        rs0 += __shfl_xor_sync(0xffffffffu, rs0, 1);
        rs0 += __shfl_xor_sync(0xffffffffu, rs0, 2);
        rs1 += __shfl_xor_sync(0xffffffffu, rs1, 1);
        rs1 += __shfl_xor_sync(0xffffffffu, rs1, 2);
        l0 = l0 * al0 + rs0;
        l1 = l1 * al1 + rs1;

        #pragma unroll
        for (int nf = 0; nf < 16; nf++) {
            o[nf][0] *= al0; o[nf][1] *= al0;
            o[nf][2] *= al1; o[nf][3] *= al1;
        }

        // ---- write P (warp-private rows), then PV ----
        {
            float* p0 = Ps + (wm + qr) * LDP;
            float* p1 = Ps + (wm + qr + 8) * LDP;
            #pragma unroll
            for (int nf = 0; nf < 8; nf++) {
                const int c = nf * 8 + 2 * qk;
                p0[c]     = tf32r(s[nf][0]);
                p0[c + 1] = tf32r(s[nf][1]);
                p1[c]     = tf32r(s[nf][2]);
                p1[c + 1] = tf32r(s[nf][3]);
            }
        }
        __syncwarp();

        #pragma unroll
        for (int ks = 0; ks < 8; ks++) {
            unsigned a[4];
            a[0] = fb(Ps[(wm + qr) * LDP + ks * 8 + qk]);
            a[1] = fb(Ps[(wm + qr + 8) * LDP + ks * 8 + qk]);
            a[2] = fb(Ps[(wm + qr) * LDP + ks * 8 + qk + 4]);
            a[3] = fb(Ps[(wm + qr + 8) * LDP + ks * 8 + qk + 4]);
            #pragma unroll
            for (int nf = 0; nf < 16; nf++) {
                unsigned b[2];
                const int rw = (ks * 8 + qk) * LDV + nf * 8 + qr;
                b[0] = fb(Vs[rw]);
                b[1] = fb(Vs[rw + 4 * LDV]);
                mma_tf32(o[nf], a, b);
            }
        }

        __syncthreads();   // all warps done reading buf jt before it is refilled
        if (jt + 2 < njt) load_kv(sbase, jt & 1, jt + 2, h, tid, Kg, Vg);
    }

    // ---- epilogue: normalize and store ----
    const float il0 = 1.f / l0;
    const float il1 = 1.f / l1;
    const int rg0 = qt * 128 + wm + qr;
    #pragma unroll
    for (int nf = 0; nf < 16; nf++) {
        const int c = h * 128 + nf * 8 + 2 * qk;
        float2 v0 = make_float2(o[nf][0] * il0, o[nf][1] * il0);
        float2 v1 = make_float2(o[nf][2] * il1, o[nf][3] * il1);
        *(float2*)(Og + (size_t)rg0 * 2048 + c)       = v0;
        *(float2*)(Og + (size_t)(rg0 + 8) * 2048 + c) = v1;
    }
}

// ---------------- launch ----------------
extern "C" void kernel_launch(void* const* d_in, const int* in_sizes, int n_in,
                              void* d_out, int out_size)
{
    const float* hs       = (const float*)d_in[0];
    const float* Wq_down  = (const float*)d_in[2];
    const float* Wq_up    = (const float*)d_in[3];
    const float* Wkv_down = (const float*)d_in[4];
    const float* Wk_up    = (const float*)d_in[5];
    const float* Wv_up    = (const float*)d_in[6];
    const float* Wo       = (const float*)d_in[7];
    float* out = (float*)d_out;

    float *q1, *q, *ckv, *k, *v, *attn;
    cudaGetSymbolAddress((void**)&q1,   g_q1);
    cudaGetSymbolAddress((void**)&q,    g_q);
    cudaGetSymbolAddress((void**)&ckv,  g_ckv);
    cudaGetSymbolAddress((void**)&k,    g_k);
    cudaGetSymbolAddress((void**)&v,    g_v);
    cudaGetSymbolAddress((void**)&attn, g_attn);

    static bool attr_set = false;
    if (!attr_set) {
        cudaFuncSetAttribute(flash_attn,
                             cudaFuncAttributeMaxDynamicSharedMemorySize,
                             FLASH_SMEM);
        attr_set = true;
    }

    // q1 = hs @ Wq_down
    gemm_tf32<false><<<dim3(1536 / 128, SEQ / 128), 256>>>(hs, Wq_down, q1, 2048, 2048, 1536, 1536);
    // q = q1 @ Wq_up
    gemm_tf32<false><<<dim3(3072 / 128, SEQ / 128), 256>>>(q1, Wq_up, q, 1536, 1536, 3072, 3072);
    // ckv = hs @ Wkv_down
    gemm_tf32<false><<<dim3(512 / 128, SEQ / 128), 256>>>(hs, Wkv_down, ckv, 2048, 2048, 512, 512);
    // k = ckv @ Wk_up  (tf32-rounded output)
    gemm_tf32<true><<<dim3(3072 / 128, SEQ / 128), 256>>>(ckv, Wk_up, k, 512, 512, 3072, 3072);
    // v = ckv @ Wv_up  (tf32-rounded output)
    gemm_tf32<true><<<dim3(2048 / 128, SEQ / 128), 256>>>(ckv, Wv_up, v, 512, 512, 2048, 2048);

    // RoPE in place on q and k (rounds outputs)
    rope_kernel<<<(SEQ * NH * 32) / 256, 256>>>(q);
    rope_kernel<<<(SEQ * NH * 32) / 256, 256>>>(k);

    // fused causal attention -> attn [SEQ, H*128]
    flash_attn<<<dim3(NH, SEQ / 128), 256, FLASH_SMEM>>>(q, k, v, attn);

    // out = attn @ Wo
    gemm_tf32<false><<<dim3(2048 / 128, SEQ / 128), 256>>>(attn, Wo, out, 2048, 2048, 2048, 2048);
}

// round 6
// speedup vs baseline: 1.8802x; 1.8802x over previous
#include <cuda_runtime.h>
#include <math.h>
#include <stdint.h>

#define SEQ 2048
#define NH 16
#define DQK 192

// ---------------- scratch (no allocations allowed) ----------------
__device__ __align__(16) float g_q1[SEQ * 1536];
__device__ __align__(16) float g_q [SEQ * 3072];
__device__ __align__(16) float g_ckv[SEQ * 512];
__device__ __align__(16) float g_k [SEQ * 3072];
__device__ __align__(16) float g_v [SEQ * 2048];
__device__ __align__(16) float g_attn[SEQ * 2048];

__device__ __forceinline__ float tf32r(float x) {
    unsigned u;
    asm("cvt.rna.tf32.f32 %0, %1;" : "=r"(u) : "f"(x));
    return __uint_as_float(u);
}
__device__ __forceinline__ unsigned fb(float x) { return __float_as_uint(x); }

__device__ __forceinline__ float ex2(float x) {
    float y;
    asm("ex2.approx.ftz.f32 %0, %1;" : "=f"(y) : "f"(x));
    return y;
}

__device__ __forceinline__ void mma_tf32(float* c, const unsigned* a, const unsigned* b) {
    asm("mma.sync.aligned.m16n8k8.row.col.f32.tf32.tf32.f32 "
        "{%0,%1,%2,%3}, {%4,%5,%6,%7}, {%8,%9}, {%0,%1,%2,%3};"
        : "+f"(c[0]), "+f"(c[1]), "+f"(c[2]), "+f"(c[3])
        : "r"(a[0]), "r"(a[1]), "r"(a[2]), "r"(a[3]), "r"(b[0]), "r"(b[1]));
}

__device__ __forceinline__ void cp16(uint32_t dst, const float* src) {
    asm volatile("cp.async.cg.shared.global [%0], [%1], 16;"
                 :: "r"(dst), "l"(__cvta_generic_to_global(src)));
}

// ---------------- shared tf32 GEMM core (128x128 tile, BK=16, 256 thr) ----------------
__device__ __forceinline__ void gemm_core(
    const float* __restrict__ A, const float* __restrict__ B, float* __restrict__ C,
    int K, int lda, int ldb, int ldc, int m0, int n0, bool rnd,
    float (*As)[16][132], float (*Bs)[16][132])
{
    const int t = threadIdx.x;
    const int am = t >> 1;
    const int ak = (t & 1) * 8;
    const int bk = t >> 4;
    const int bn = (t & 15) * 8;

    const int lane = t & 31;
    const int warp = t >> 5;
    const int wm = (warp >> 2) * 64;
    const int wn = (warp & 3) * 32;
    const int qk = lane & 3;
    const int qr = lane >> 2;

    float acc[4][4][4] = {};
    float4 ra0, ra1, rb0, rb1;

    {
        const float* pa = A + (size_t)(m0 + am) * lda + ak;
        ra0 = *(const float4*)pa; ra1 = *(const float4*)(pa + 4);
        const float* pb = B + (size_t)bk * ldb + n0 + bn;
        rb0 = *(const float4*)pb; rb1 = *(const float4*)(pb + 4);
        As[0][ak + 0][am] = tf32r(ra0.x); As[0][ak + 1][am] = tf32r(ra0.y);
        As[0][ak + 2][am] = tf32r(ra0.z); As[0][ak + 3][am] = tf32r(ra0.w);
        As[0][ak + 4][am] = tf32r(ra1.x); As[0][ak + 5][am] = tf32r(ra1.y);
        As[0][ak + 6][am] = tf32r(ra1.z); As[0][ak + 7][am] = tf32r(ra1.w);
        Bs[0][bk][bn + 0] = tf32r(rb0.x); Bs[0][bk][bn + 1] = tf32r(rb0.y);
        Bs[0][bk][bn + 2] = tf32r(rb0.z); Bs[0][bk][bn + 3] = tf32r(rb0.w);
        Bs[0][bk][bn + 4] = tf32r(rb1.x); Bs[0][bk][bn + 5] = tf32r(rb1.y);
        Bs[0][bk][bn + 6] = tf32r(rb1.z); Bs[0][bk][bn + 7] = tf32r(rb1.w);
    }
    __syncthreads();

    int buf = 0;
    for (int kt = 0; kt < K; kt += 16) {
        const bool more = (kt + 16) < K;
        if (more) {
            const float* pa = A + (size_t)(m0 + am) * lda + kt + 16 + ak;
            ra0 = *(const float4*)pa; ra1 = *(const float4*)(pa + 4);
            const float* pb = B + (size_t)(kt + 16 + bk) * ldb + n0 + bn;
            rb0 = *(const float4*)pb; rb1 = *(const float4*)(pb + 4);
        }

        #pragma unroll
        for (int k8 = 0; k8 < 16; k8 += 8) {
            unsigned af[4][4], bfr[4][2];
            #pragma unroll
            for (int mi = 0; mi < 4; mi++) {
                const int m = wm + mi * 16 + qr;
                af[mi][0] = fb(As[buf][k8 + qk][m]);
                af[mi][1] = fb(As[buf][k8 + qk][m + 8]);
                af[mi][2] = fb(As[buf][k8 + qk + 4][m]);
                af[mi][3] = fb(As[buf][k8 + qk + 4][m + 8]);
            }
            #pragma unroll
            for (int ni = 0; ni < 4; ni++) {
                const int n = wn + ni * 8 + qr;
                bfr[ni][0] = fb(Bs[buf][k8 + qk][n]);
                bfr[ni][1] = fb(Bs[buf][k8 + qk + 4][n]);
            }
            #pragma unroll
            for (int mi = 0; mi < 4; mi++)
                #pragma unroll
                for (int ni = 0; ni < 4; ni++)
                    mma_tf32(acc[mi][ni], af[mi], bfr[ni]);
        }

        if (more) {
            const int nb = buf ^ 1;
            As[nb][ak + 0][am] = tf32r(ra0.x); As[nb][ak + 1][am] = tf32r(ra0.y);
            As[nb][ak + 2][am] = tf32r(ra0.z); As[nb][ak + 3][am] = tf32r(ra0.w);
            As[nb][ak + 4][am] = tf32r(ra1.x); As[nb][ak + 5][am] = tf32r(ra1.y);
            As[nb][ak + 6][am] = tf32r(ra1.z); As[nb][ak + 7][am] = tf32r(ra1.w);
            Bs[nb][bk][bn + 0] = tf32r(rb0.x); Bs[nb][bk][bn + 1] = tf32r(rb0.y);
            Bs[nb][bk][bn + 2] = tf32r(rb0.z); Bs[nb][bk][bn + 3] = tf32r(rb0.w);
            Bs[nb][bk][bn + 4] = tf32r(rb1.x); Bs[nb][bk][bn + 5] = tf32r(rb1.y);
            Bs[nb][bk][bn + 6] = tf32r(rb1.z); Bs[nb][bk][bn + 7] = tf32r(rb1.w);
            __syncthreads();
            buf ^= 1;
        }
    }

    #pragma unroll
    for (int mi = 0; mi < 4; mi++) {
        #pragma unroll
        for (int ni = 0; ni < 4; ni++) {
            const int m = m0 + wm + mi * 16 + qr;
            const int n = n0 + wn + ni * 8 + 2 * qk;
            float2 v0, v1;
            if (rnd) {
                v0.x = tf32r(acc[mi][ni][0]); v0.y = tf32r(acc[mi][ni][1]);
                v1.x = tf32r(acc[mi][ni][2]); v1.y = tf32r(acc[mi][ni][3]);
            } else {
                v0.x = acc[mi][ni][0]; v0.y = acc[mi][ni][1];
                v1.x = acc[mi][ni][2]; v1.y = acc[mi][ni][3];
            }
            *(float2*)(C + (size_t)m * ldc + n)       = v0;
            *(float2*)(C + (size_t)(m + 8) * ldc + n) = v1;
        }
    }
}

// stage 1: hs @ [Wq_down | Wkv_down]  (256 CTAs)
__global__ __launch_bounds__(256, 2) void gemm_stage1(
    const float* __restrict__ hs, const float* __restrict__ Wq_down,
    const float* __restrict__ Wkv_down, float* __restrict__ q1, float* __restrict__ ckv)
{
    __shared__ float As[2][16][132];
    __shared__ float Bs[2][16][132];
    const int bid = blockIdx.x;
    const int m0 = (bid >> 4) * 128;
    const int nt = bid & 15;
    if (nt < 12)
        gemm_core(hs, Wq_down, q1, 2048, 2048, 1536, 1536, m0, nt * 128, false, As, Bs);
    else
        gemm_core(hs, Wkv_down, ckv, 2048, 2048, 512, 512, m0, (nt - 12) * 128, false, As, Bs);
}

// stage 2: q1@Wq_up | ckv@Wk_up | ckv@Wv_up  (1024 CTAs)
__global__ __launch_bounds__(256, 2) void gemm_stage2(
    const float* __restrict__ q1, const float* __restrict__ Wq_up, float* __restrict__ q,
    const float* __restrict__ ckv, const float* __restrict__ Wk_up, float* __restrict__ k,
    const float* __restrict__ Wv_up, float* __restrict__ v)
{
    __shared__ float As[2][16][132];
    __shared__ float Bs[2][16][132];
    const int bid = blockIdx.x;
    if (bid < 384) {
        gemm_core(q1, Wq_up, q, 1536, 1536, 3072, 3072,
                  (bid / 24) * 128, (bid % 24) * 128, true, As, Bs);
    } else if (bid < 768) {
        const int b = bid - 384;
        gemm_core(ckv, Wk_up, k, 512, 512, 3072, 3072,
                  (b / 24) * 128, (b % 24) * 128, true, As, Bs);
    } else {
        const int b = bid - 768;
        gemm_core(ckv, Wv_up, v, 512, 512, 2048, 2048,
                  (b / 16) * 128, (b % 16) * 128, true, As, Bs);
    }
}

// stage 3: attn @ Wo
__global__ __launch_bounds__(256, 2) void gemm_stage3(
    const float* __restrict__ attn, const float* __restrict__ Wo, float* __restrict__ out)
{
    __shared__ float As[2][16][132];
    __shared__ float Bs[2][16][132];
    const int bid = blockIdx.x;
    gemm_core(attn, Wo, out, 2048, 2048, 2048, 2048,
              (bid >> 4) * 128, (bid & 15) * 128, false, As, Bs);
}

// ---------------- RoPE (q and k in one launch; outputs tf32-rounded) ----------------
__global__ void rope_kernel(float* __restrict__ Q, float* __restrict__ K)
{
    float* X = blockIdx.y ? K : Q;
    int idx = blockIdx.x * blockDim.x + threadIdx.x;   // SEQ*NH*32 total
    int j = idx & 31;
    int h = (idx >> 5) & (NH - 1);
    int t = idx >> 9;
    float* p = X + (size_t)t * 3072 + h * DQK + 128;
    float inv = powf(10000.0f, -(float)j / 32.0f);
    float ang = (float)t * inv;
    float s, c;
    sincosf(ang, &s, &c);
    float x1 = p[j], x2 = p[j + 32];
    p[j]      = tf32r(x1 * c - x2 * s);
    p[j + 32] = tf32r(x2 * c + x1 * s);
}

// ---------------- fused causal flash attention (v3) ----------------
// Per CTA: one head, 128 Q rows resident in smem. 32-row K/V tiles,
// cp.async double-buffered. 8 warps x 16 Q rows.
#define LDQ 196
#define LDK 196
#define LDV 136
#define LDP 36
#define KT  32
#define OFF_K0 (128 * LDQ)                 // 25088
#define KBUF   (KT * LDK)                  // 6272
#define OFF_V0 (OFF_K0 + 2 * KBUF)         // 37632
#define VBUF   (KT * LDV)                  // 4352
#define OFF_P  (OFF_V0 + 2 * VBUF)         // 46336
#define FLASH_SMEM ((OFF_P + 128 * LDP) * 4)   // 203776 bytes

__device__ __forceinline__ void load_kv32(
    uint32_t sbase, int buf, int jt, int h, int tid,
    const float* __restrict__ Kg, const float* __restrict__ Vg)
{
    uint32_t kdst = sbase + (OFF_K0 + buf * KBUF) * 4;
    const float* ksrc = Kg + (size_t)(jt * KT) * 3072 + h * DQK;
    #pragma unroll
    for (int i = 0; i < 6; i++) {
        int idx = tid + i * 256;            // 1536 16B chunks (48/row)
        int r = idx / 48, c = idx - r * 48;
        cp16(kdst + (r * LDK + c * 4) * 4, ksrc + (size_t)r * 3072 + c * 4);
    }
    uint32_t vdst = sbase + (OFF_V0 + buf * VBUF) * 4;
    const float* vsrc = Vg + (size_t)(jt * KT) * 2048 + h * 128;
    #pragma unroll
    for (int i = 0; i < 4; i++) {
        int idx = tid + i * 256;            // 1024 16B chunks (32/row)
        int r = idx >> 5, c = idx & 31;
        cp16(vdst + (r * LDV + c * 4) * 4, vsrc + (size_t)r * 2048 + c * 4);
    }
    asm volatile("cp.async.commit_group;");
}

__global__ __launch_bounds__(256, 1) void flash_attn(
    const float* __restrict__ Qg, const float* __restrict__ Kg,
    const float* __restrict__ Vg, float* __restrict__ Og)
{
    extern __shared__ float sm[];
    const uint32_t sbase = (uint32_t)__cvta_generic_to_shared(sm);
    float* Qs = sm;

    const int h   = blockIdx.x;
    const int qt  = 15 - blockIdx.y;      // long CTAs first
    const int tid = threadIdx.x;
    const int lane = tid & 31;
    const int warp = tid >> 5;
    const int qr = lane >> 2;
    const int qk = lane & 3;
    const int wm = warp * 16;

    const float cs = 0.10411758f;         // log2(e)/sqrt(192)

    // ---- load Q tile [128 x 192] raw (producer already tf32-rounded) ----
    #pragma unroll
    for (int i = 0; i < 24; i++) {
        int idx = tid + i * 256;           // 6144 float4 chunks (48/row)
        int r = idx / 48, c = idx - r * 48;
        float4 v4 = *(const float4*)(Qg + (size_t)(qt * 128 + r) * 3072 + h * DQK + c * 4);
        *(float4*)(Qs + r * LDQ + c * 4) = v4;
    }

    const int njt = 4 * qt + 4;
    load_kv32(sbase, 0, 0, h, tid, Kg, Vg);
    load_kv32(sbase, 1, 1, h, tid, Kg, Vg);

    float o[16][4];
    #pragma unroll
    for (int i = 0; i < 16; i++)
        #pragma unroll
        for (int j = 0; j < 4; j++) o[i][j] = 0.f;
    float m0 = -1e30f, m1 = -1e30f, l0 = 0.f, l1 = 0.f;

    const float* Qr0 = Qs + (wm + qr) * LDQ;
    const float* Qr1 = Qs + (wm + qr + 8) * LDQ;

    for (int jt = 0; jt < njt; jt++) {
        if (jt + 2 < njt) asm volatile("cp.async.wait_group 1;");
        else              asm volatile("cp.async.wait_group 0;");
        __syncthreads();   // buffer jt visible to all (also covers Q load on jt==0)

        const float* Ks = sm + OFF_K0 + (jt & 1) * KBUF;
        const float* Vs = sm + OFF_V0 + (jt & 1) * VBUF;
        float* Ps = sm + OFF_P;

        // ---- S = Q K^T : warp rows [wm, wm+16), cols [0,32) ----
        float s[4][4];
        #pragma unroll
        for (int i = 0; i < 4; i++)
            #pragma unroll
            for (int j = 0; j < 4; j++) s[i][j] = 0.f;

        #pragma unroll
        for (int ks = 0; ks < 24; ks++) {
            unsigned a[4];
            a[0] = fb(Qr0[ks * 8 + qk]);
            a[1] = fb(Qr1[ks * 8 + qk]);
            a[2] = fb(Qr0[ks * 8 + qk + 4]);
            a[3] = fb(Qr1[ks * 8 + qk + 4]);
            #pragma unroll
            for (int nf = 0; nf < 4; nf++) {
                unsigned b[2];
                const int row = (nf * 8 + qr) * LDK + ks * 8 + qk;
                b[0] = fb(Ks[row]);
                b[1] = fb(Ks[row + 4]);
                mma_tf32(s[nf], a, b);
            }
        }

        // ---- causal mask (tiles at/after the diagonal) ----
        const int rg0 = qt * 128 + wm + qr;
        if (jt >= 4 * qt) {
            #pragma unroll
            for (int nf = 0; nf < 4; nf++) {
                const int cg = jt * KT + nf * 8 + 2 * qk;
                if (cg     > rg0)     s[nf][0] = -1e30f;
                if (cg + 1 > rg0)     s[nf][1] = -1e30f;
                if (cg     > rg0 + 8) s[nf][2] = -1e30f;
                if (cg + 1 > rg0 + 8) s[nf][3] = -1e30f;
            }
        }

        // ---- online softmax ----
        float mx0 = -1e30f, mx1 = -1e30f;
        #pragma unroll
        for (int nf = 0; nf < 4; nf++) {
            mx0 = fmaxf(mx0, fmaxf(s[nf][0], s[nf][1]));
            mx1 = fmaxf(mx1, fmaxf(s[nf][2], s[nf][3]));
        }
        mx0 = fmaxf(mx0, __shfl_xor_sync(0xffffffffu, mx0, 1));
        mx0 = fmaxf(mx0, __shfl_xor_sync(0xffffffffu, mx0, 2));
        mx1 = fmaxf(mx1, __shfl_xor_sync(0xffffffffu, mx1, 1));
        mx1 = fmaxf(mx1, __shfl_xor_sync(0xffffffffu, mx1, 2));

        const float mn0 = fmaxf(m0, mx0);
        const float mn1 = fmaxf(m1, mx1);
        const float al0 = ex2((m0 - mn0) * cs);
        const float al1 = ex2((m1 - mn1) * cs);
        m0 = mn0; m1 = mn1;

        float rs0 = 0.f, rs1 = 0.f;
        #pragma unroll
        for (int nf = 0; nf < 4; nf++) {
            s[nf][0] = ex2((s[nf][0] - mn0) * cs);
            s[nf][1] = ex2((s[nf][1] - mn0) * cs);
            s[nf][2] = ex2((s[nf][2] - mn1) * cs);
            s[nf][3] = ex2((s[nf][3] - mn1) * cs);
            rs0 += s[nf][0] + s[nf][1];
            rs1 += s[nf][2] + s[nf][3];
        }
        rs0 += __shfl_xor_sync(0xffffffffu, rs0, 1);
        rs0 += __shfl_xor_sync(0xffffffffu, rs0, 2);
        rs1 += __shfl_xor_sync(0xffffffffu, rs1, 1);
        rs1 += __shfl_xor_sync(0xffffffffu, rs1, 2);
        l0 = l0 * al0 + rs0;
        l1 = l1 * al1 + rs1;

        #pragma unroll
        for (int nf = 0; nf < 16; nf++) {
            o[nf][0] *= al0; o[nf][1] *= al0;
            o[nf][2] *= al1; o[nf][3] *= al1;
        }

        // ---- write P (warp-private rows, tf32-rounded), then PV ----
        {
            float* p0 = Ps + (wm + qr) * LDP;
            float* p1 = Ps + (wm + qr + 8) * LDP;
            #pragma unroll
            for (int nf = 0; nf < 4; nf++) {
                const int c = nf * 8 + 2 * qk;
                p0[c]     = tf32r(s[nf][0]);
                p0[c + 1] = tf32r(s[nf][1]);
                p1[c]     = tf32r(s[nf][2]);
                p1[c + 1] = tf32r(s[nf][3]);
            }
        }
        __syncwarp();

        #pragma unroll
        for (int ks = 0; ks < 4; ks++) {
            unsigned a[4];
            a[0] = fb(Ps[(wm + qr) * LDP + ks * 8 + qk]);
            a[1] = fb(Ps[(wm + qr + 8) * LDP + ks * 8 + qk]);
            a[2] = fb(Ps[(wm + qr) * LDP + ks * 8 + qk + 4]);
            a[3] = fb(Ps[(wm + qr + 8) * LDP + ks * 8 + qk + 4]);
            #pragma unroll
            for (int nf = 0; nf < 16; nf++) {
                unsigned b[2];
                const int rw = (ks * 8 + qk) * LDV + nf * 8 + qr;
                b[0] = fb(Vs[rw]);
                b[1] = fb(Vs[rw + 4 * LDV]);
                mma_tf32(o[nf], a, b);
            }
        }

        __syncthreads();   // all warps done with buffer jt before refill
        if (jt + 2 < njt) load_kv32(sbase, jt & 1, jt + 2, h, tid, Kg, Vg);
    }

    // ---- epilogue: normalize and store ----
    const float il0 = 1.f / l0;
    const float il1 = 1.f / l1;
    const int rg0 = qt * 128 + wm + qr;
    #pragma unroll
    for (int nf = 0; nf < 16; nf++) {
        const int c = h * 128 + nf * 8 + 2 * qk;
        float2 v0 = make_float2(o[nf][0] * il0, o[nf][1] * il0);
        float2 v1 = make_float2(o[nf][2] * il1, o[nf][3] * il1);
        *(float2*)(Og + (size_t)rg0 * 2048 + c)       = v0;
        *(float2*)(Og + (size_t)(rg0 + 8) * 2048 + c) = v1;
    }
}

// ---------------- launch ----------------
extern "C" void kernel_launch(void* const* d_in, const int* in_sizes, int n_in,
                              void* d_out, int out_size)
{
    const float* hs       = (const float*)d_in[0];
    const float* Wq_down  = (const float*)d_in[2];
    const float* Wq_up    = (const float*)d_in[3];
    const float* Wkv_down = (const float*)d_in[4];
    const float* Wk_up    = (const float*)d_in[5];
    const float* Wv_up    = (const float*)d_in[6];
    const float* Wo       = (const float*)d_in[7];
    float* out = (float*)d_out;

    float *q1, *q, *ckv, *k, *v, *attn;
    cudaGetSymbolAddress((void**)&q1,   g_q1);
    cudaGetSymbolAddress((void**)&q,    g_q);
    cudaGetSymbolAddress((void**)&ckv,  g_ckv);
    cudaGetSymbolAddress((void**)&k,    g_k);
    cudaGetSymbolAddress((void**)&v,    g_v);
    cudaGetSymbolAddress((void**)&attn, g_attn);

    static bool attr_set = false;
    if (!attr_set) {
        cudaFuncSetAttribute(flash_attn,
                             cudaFuncAttributeMaxDynamicSharedMemorySize,
                             FLASH_SMEM);
        attr_set = true;
    }

    gemm_stage1<<<256, 256>>>(hs, Wq_down, Wkv_down, q1, ckv);
    gemm_stage2<<<1024, 256>>>(q1, Wq_up, q, ckv, Wk_up, k, Wv_up, v);
    rope_kernel<<<dim3(4096, 2), 256>>>(q, k);   // SEQ*NH*32 threads per tensor
    flash_attn<<<dim3(NH, SEQ / 128), 256, FLASH_SMEM>>>(q, k, v, attn);
    gemm_stage3<<<256, 256>>>(attn, Wo, out);
}

// round 11
// speedup vs baseline: 2.4001x; 1.2765x over previous
#include <cuda_runtime.h>
#include <math.h>
#include <stdint.h>

#define SEQ 2048
#define NH 16
#define DQK 192

// ---------------- scratch (no allocations allowed) ----------------
__device__ __align__(16) float g_hs  [SEQ * 2048];
__device__ __align__(16) float g_q1  [SEQ * 1536];
__device__ __align__(16) float g_q   [SEQ * 3072];
__device__ __align__(16) float g_ckv [SEQ * 512];
__device__ __align__(16) float g_k   [SEQ * 3072];
__device__ __align__(16) float g_v   [SEQ * 2048];
__device__ __align__(16) float g_attn[SEQ * 2048];
// transposed + tf32-rounded weights [n][k]
__device__ __align__(16) float g_Tqd [1536 * 2048];
__device__ __align__(16) float g_Tqu [3072 * 1536];
__device__ __align__(16) float g_Tkvd[512 * 2048];
__device__ __align__(16) float g_Tku [3072 * 512];
__device__ __align__(16) float g_Tvu [2048 * 512];
__device__ __align__(16) float g_Two [2048 * 2048];

__device__ __forceinline__ float tf32r(float x) {
    unsigned u;
    asm("cvt.rna.tf32.f32 %0, %1;" : "=r"(u) : "f"(x));
    return __uint_as_float(u);
}
__device__ __forceinline__ unsigned fb(float x) { return __float_as_uint(x); }

__device__ __forceinline__ float ex2(float x) {
    float y;
    asm("ex2.approx.ftz.f32 %0, %1;" : "=f"(y) : "f"(x));
    return y;
}

__device__ __forceinline__ void mma_tf32(float* c, const unsigned* a, const unsigned* b) {
    asm("mma.sync.aligned.m16n8k8.row.col.f32.tf32.tf32.f32 "
        "{%0,%1,%2,%3}, {%4,%5,%6,%7}, {%8,%9}, {%0,%1,%2,%3};"
        : "+f"(c[0]), "+f"(c[1]), "+f"(c[2]), "+f"(c[3])
        : "r"(a[0]), "r"(a[1]), "r"(a[2]), "r"(a[3]), "r"(b[0]), "r"(b[1]));
}

__device__ __forceinline__ void cp16(uint32_t dst, const float* src) {
    asm volatile("cp.async.cg.shared.global [%0], [%1], 16;"
                 :: "r"(dst), "l"(__cvta_generic_to_global(src)));
}

// ---------------- prep: transpose+round weights, round-copy hs ----------------
// 32x32 tiles, blockDim (32,8). Tile ranges per matrix hardcoded.
__global__ void prep_kernel(
    const float* __restrict__ hs,
    const float* __restrict__ Wqd, const float* __restrict__ Wqu,
    const float* __restrict__ Wkvd, const float* __restrict__ Wku,
    const float* __restrict__ Wvu, const float* __restrict__ Wo)
{
    __shared__ float tl[32][33];
    int b = blockIdx.x;
    const float* in; float* out; int K, N, t; bool trans = true;
    if      (b < 3072)  { in = Wqd;  out = g_Tqd;  K = 2048; N = 1536; t = b; }
    else if (b < 7680)  { in = Wqu;  out = g_Tqu;  K = 1536; N = 3072; t = b - 3072; }
    else if (b < 8704)  { in = Wkvd; out = g_Tkvd; K = 2048; N = 512;  t = b - 7680; }
    else if (b < 10240) { in = Wku;  out = g_Tku;  K = 512;  N = 3072; t = b - 8704; }
    else if (b < 11264) { in = Wvu;  out = g_Tvu;  K = 512;  N = 2048; t = b - 10240; }
    else if (b < 15360) { in = Wo;   out = g_Two;  K = 2048; N = 2048; t = b - 11264; }
    else                { in = hs;   out = g_hs;   K = 2048; N = 2048; t = b - 15360; trans = false; }

    const int ntn = N >> 5;
    const int k0 = (t / ntn) << 5;
    const int n0 = (t % ntn) << 5;
    const int tx = threadIdx.x;
    #pragma unroll
    for (int i = 0; i < 4; i++) {
        int ty = threadIdx.y * 4 + i;
        tl[ty][tx] = in[(size_t)(k0 + ty) * N + n0 + tx];
    }
    __syncthreads();
    #pragma unroll
    for (int i = 0; i < 4; i++) {
        int ty = threadIdx.y * 4 + i;
        if (trans) out[(size_t)(n0 + ty) * K + k0 + tx] = tf32r(tl[tx][ty]);
        else       out[(size_t)(k0 + ty) * N + n0 + tx] = tf32r(tl[ty][tx]);
    }
}

// ---------------- gemm v2: NT, cp.async 4-stage, 128x128 tile, BK=16 ----------------
// A [m][k] row-major, Bt [n][k] row-major, both pre-rounded to tf32.
#define GLD 20
#define GSTG (128 * GLD)             // floats per stage per operand
#define GEMM_SMEM (8 * GSTG * 4)     // 81920 bytes

__device__ __forceinline__ void gemm2_core(
    const float* __restrict__ A, const float* __restrict__ Bt, float* __restrict__ C,
    int K, int lda, int ldb, int ldc, int m0, int n0, bool rnd,
    float* sa, float* sb)
{
    const int t = threadIdx.x;
    const int lane = t & 31, warp = t >> 5;
    const int wm = (warp >> 2) * 64, wn = (warp & 3) * 32;
    const int qk = lane & 3, qr = lane >> 2;
    const uint32_t sa_u = (uint32_t)__cvta_generic_to_shared(sa);
    const uint32_t sb_u = (uint32_t)__cvta_generic_to_shared(sb);

    const int nt = K >> 4;
    const int lrow = t >> 2;            // 0..63? no: t>>2 in [0,63]; need rows 0..127
    const int lkc  = (t & 3) << 2;

    // per stage: A 512 chunks, B 512 chunks; thread does idx = t, t+256 for each
    #define G2_ISSUE(stg, kt)                                                        \
        do {                                                                         \
            _Pragma("unroll")                                                        \
            for (int i = 0; i < 2; i++) {                                            \
                int idx = t + i * 256;                                               \
                int row = idx >> 2, kc = (idx & 3) << 2;                             \
                cp16(sa_u + ((stg) * GSTG + row * GLD + kc) * 4,                     \
                     A + (size_t)(m0 + row) * lda + (kt) + kc);                      \
                cp16(sb_u + ((stg) * GSTG + row * GLD + kc) * 4,                     \
                     Bt + (size_t)(n0 + row) * ldb + (kt) + kc);                     \
            }                                                                        \
            asm volatile("cp.async.commit_group;");                                  \
        } while (0)

    (void)lrow; (void)lkc;
    G2_ISSUE(0, 0);
    G2_ISSUE(1, 16);
    G2_ISSUE(2, 32);

    float acc[4][4][4] = {};

    for (int tt = 0; tt < nt; tt++) {
        const int rem = nt - 1 - tt;
        if (rem >= 2)      asm volatile("cp.async.wait_group 2;");
        else if (rem == 1) asm volatile("cp.async.wait_group 1;");
        else               asm volatile("cp.async.wait_group 0;");
        __syncthreads();

        if (tt + 3 < nt) G2_ISSUE((tt + 3) & 3, (tt + 3) << 4);

        const float* at = sa + (tt & 3) * GSTG;
        const float* bt = sb + (tt & 3) * GSTG;

        #pragma unroll
        for (int k8 = 0; k8 < 16; k8 += 8) {
            unsigned af[4][4], bf[4][2];
            #pragma unroll
            for (int mi = 0; mi < 4; mi++) {
                const float* r0 = at + (wm + mi * 16 + qr) * GLD + k8;
                af[mi][0] = fb(r0[qk]);
                af[mi][1] = fb(r0[8 * GLD + qk]);
                af[mi][2] = fb(r0[qk + 4]);
                af[mi][3] = fb(r0[8 * GLD + qk + 4]);
            }
            #pragma unroll
            for (int ni = 0; ni < 4; ni++) {
                const float* rn = bt + (wn + ni * 8 + qr) * GLD + k8;
                bf[ni][0] = fb(rn[qk]);
                bf[ni][1] = fb(rn[qk + 4]);
            }
            #pragma unroll
            for (int mi = 0; mi < 4; mi++)
                #pragma unroll
                for (int ni = 0; ni < 4; ni++)
                    mma_tf32(acc[mi][ni], af[mi], bf[ni]);
        }
    }

    #pragma unroll
    for (int mi = 0; mi < 4; mi++) {
        #pragma unroll
        for (int ni = 0; ni < 4; ni++) {
            const int m = m0 + wm + mi * 16 + qr;
            const int n = n0 + wn + ni * 8 + 2 * qk;
            float2 v0, v1;
            if (rnd) {
                v0.x = tf32r(acc[mi][ni][0]); v0.y = tf32r(acc[mi][ni][1]);
                v1.x = tf32r(acc[mi][ni][2]); v1.y = tf32r(acc[mi][ni][3]);
            } else {
                v0.x = acc[mi][ni][0]; v0.y = acc[mi][ni][1];
                v1.x = acc[mi][ni][2]; v1.y = acc[mi][ni][3];
            }
            *(float2*)(C + (size_t)m * ldc + n)       = v0;
            *(float2*)(C + (size_t)(m + 8) * ldc + n) = v1;
        }
    }
    #undef G2_ISSUE
}

// stage 1: hs_r @ [Wq_down | Wkv_down]^T  (256 CTAs)
__global__ __launch_bounds__(256, 2) void gemm_stage1(float* __restrict__ q1, float* __restrict__ ckv)
{
    extern __shared__ float sm2[];
    const int bid = blockIdx.x;
    const int m0 = (bid >> 4) * 128;
    const int nt = bid & 15;
    if (nt < 12)
        gemm2_core(g_hs, g_Tqd, q1, 2048, 2048, 2048, 1536, m0, nt * 128, true, sm2, sm2 + 4 * GSTG);
    else
        gemm2_core(g_hs, g_Tkvd, ckv, 2048, 2048, 2048, 512, m0, (nt - 12) * 128, true, sm2, sm2 + 4 * GSTG);
}

// stage 2: q1@Wq_up^T | ckv@Wk_up^T | ckv@Wv_up^T  (1024 CTAs)
__global__ __launch_bounds__(256, 2) void gemm_stage2(
    const float* __restrict__ q1, float* __restrict__ q,
    const float* __restrict__ ckv, float* __restrict__ k, float* __restrict__ v)
{
    extern __shared__ float sm2[];
    const int bid = blockIdx.x;
    if (bid < 384) {
        gemm2_core(q1, g_Tqu, q, 1536, 1536, 1536, 3072,
                   (bid / 24) * 128, (bid % 24) * 128, true, sm2, sm2 + 4 * GSTG);
    } else if (bid < 768) {
        const int b = bid - 384;
        gemm2_core(ckv, g_Tku, k, 512, 512, 512, 3072,
                   (b / 24) * 128, (b % 24) * 128, true, sm2, sm2 + 4 * GSTG);
    } else {
        const int b = bid - 768;
        gemm2_core(ckv, g_Tvu, v, 512, 512, 512, 2048,
                   (b / 16) * 128, (b % 16) * 128, true, sm2, sm2 + 4 * GSTG);
    }
}

// stage 3: attn @ Wo^T  (256 CTAs)
__global__ __launch_bounds__(256, 2) void gemm_stage3(
    const float* __restrict__ attn, float* __restrict__ out)
{
    extern __shared__ float sm2[];
    const int bid = blockIdx.x;
    gemm2_core(attn, g_Two, out, 2048, 2048, 2048, 2048,
               (bid >> 4) * 128, (bid & 15) * 128, false, sm2, sm2 + 4 * GSTG);
}

// ---------------- RoPE (q and k in one launch; outputs tf32-rounded) ----------------
__global__ void rope_kernel(float* __restrict__ Q, float* __restrict__ K)
{
    float* X = blockIdx.y ? K : Q;
    int idx = blockIdx.x * blockDim.x + threadIdx.x;   // SEQ*NH*32 total
    int j = idx & 31;
    int h = (idx >> 5) & (NH - 1);
    int t = idx >> 9;
    float* p = X + (size_t)t * 3072 + h * DQK + 128;
    float inv = powf(10000.0f, -(float)j / 32.0f);
    float ang = (float)t * inv;
    float s, c;
    sincosf(ang, &s, &c);
    float x1 = p[j], x2 = p[j + 32];
    p[j]      = tf32r(x1 * c - x2 * s);
    p[j + 32] = tf32r(x2 * c + x1 * s);
}

// ---------------- fused causal flash attention (v3) ----------------
#define LDQ 196
#define LDK 196
#define LDV 136
#define LDP 36
#define KT  32
#define OFF_K0 (128 * LDQ)
#define KBUF   (KT * LDK)
#define OFF_V0 (OFF_K0 + 2 * KBUF)
#define VBUF   (KT * LDV)
#define OFF_P  (OFF_V0 + 2 * VBUF)
#define FLASH_SMEM ((OFF_P + 128 * LDP) * 4)

__device__ __forceinline__ void load_kv32(
    uint32_t sbase, int buf, int jt, int h, int tid,
    const float* __restrict__ Kg, const float* __restrict__ Vg)
{
    uint32_t kdst = sbase + (OFF_K0 + buf * KBUF) * 4;
    const float* ksrc = Kg + (size_t)(jt * KT) * 3072 + h * DQK;
    #pragma unroll
    for (int i = 0; i < 6; i++) {
        int idx = tid + i * 256;
        int r = idx / 48, c = idx - r * 48;
        cp16(kdst + (r * LDK + c * 4) * 4, ksrc + (size_t)r * 3072 + c * 4);
    }
    uint32_t vdst = sbase + (OFF_V0 + buf * VBUF) * 4;
    const float* vsrc = Vg + (size_t)(jt * KT) * 2048 + h * 128;
    #pragma unroll
    for (int i = 0; i < 4; i++) {
        int idx = tid + i * 256;
        int r = idx >> 5, c = idx & 31;
        cp16(vdst + (r * LDV + c * 4) * 4, vsrc + (size_t)r * 2048 + c * 4);
    }
    asm volatile("cp.async.commit_group;");
}

__global__ __launch_bounds__(256, 1) void flash_attn(
    const float* __restrict__ Qg, const float* __restrict__ Kg,
    const float* __restrict__ Vg, float* __restrict__ Og)
{
    extern __shared__ float sm[];
    const uint32_t sbase = (uint32_t)__cvta_generic_to_shared(sm);
    float* Qs = sm;

    const int h   = blockIdx.x;
    const int qt  = 15 - blockIdx.y;
    const int tid = threadIdx.x;
    const int lane = tid & 31;
    const int warp = tid >> 5;
    const int qr = lane >> 2;
    const int qk = lane & 3;
    const int wm = warp * 16;

    const float cs = 0.10411758f;

    #pragma unroll
    for (int i = 0; i < 24; i++) {
        int idx = tid + i * 256;
        int r = idx / 48, c = idx - r * 48;
        float4 v4 = *(const float4*)(Qg + (size_t)(qt * 128 + r) * 3072 + h * DQK + c * 4);
        *(float4*)(Qs + r * LDQ + c * 4) = v4;
    }

    const int njt = 4 * qt + 4;
    load_kv32(sbase, 0, 0, h, tid, Kg, Vg);
    load_kv32(sbase, 1, 1, h, tid, Kg, Vg);

    float o[16][4];
    #pragma unroll
    for (int i = 0; i < 16; i++)
        #pragma unroll
        for (int j = 0; j < 4; j++) o[i][j] = 0.f;
    float m0 = -1e30f, m1 = -1e30f, l0 = 0.f, l1 = 0.f;

    const float* Qr0 = Qs + (wm + qr) * LDQ;
    const float* Qr1 = Qs + (wm + qr + 8) * LDQ;

    for (int jt = 0; jt < njt; jt++) {
        if (jt + 2 < njt) asm volatile("cp.async.wait_group 1;");
        else              asm volatile("cp.async.wait_group 0;");
        __syncthreads();

        const float* Ks = sm + OFF_K0 + (jt & 1) * KBUF;
        const float* Vs = sm + OFF_V0 + (jt & 1) * VBUF;
        float* Ps = sm + OFF_P;

        float s[4][4];
        #pragma unroll
        for (int i = 0; i < 4; i++)
            #pragma unroll
            for (int j = 0; j < 4; j++) s[i][j] = 0.f;

        #pragma unroll
        for (int ks = 0; ks < 24; ks++) {
            unsigned a[4];
            a[0] = fb(Qr0[ks * 8 + qk]);
            a[1] = fb(Qr1[ks * 8 + qk]);
            a[2] = fb(Qr0[ks * 8 + qk + 4]);
            a[3] = fb(Qr1[ks * 8 + qk + 4]);
            #pragma unroll
            for (int nf = 0; nf < 4; nf++) {
                unsigned b[2];
                const int row = (nf * 8 + qr) * LDK + ks * 8 + qk;
                b[0] = fb(Ks[row]);
                b[1] = fb(Ks[row + 4]);
                mma_tf32(s[nf], a, b);
            }
        }

        const int rg0 = qt * 128 + wm + qr;
        if (jt >= 4 * qt) {
            #pragma unroll
            for (int nf = 0; nf < 4; nf++) {
                const int cg = jt * KT + nf * 8 + 2 * qk;
                if (cg     > rg0)     s[nf][0] = -1e30f;
                if (cg + 1 > rg0)     s[nf][1] = -1e30f;
                if (cg     > rg0 + 8) s[nf][2] = -1e30f;
                if (cg + 1 > rg0 + 8) s[nf][3] = -1e30f;
            }
        }

        float mx0 = -1e30f, mx1 = -1e30f;
        #pragma unroll
        for (int nf = 0; nf < 4; nf++) {
            mx0 = fmaxf(mx0, fmaxf(s[nf][0], s[nf][1]));
            mx1 = fmaxf(mx1, fmaxf(s[nf][2], s[nf][3]));
        }
        mx0 = fmaxf(mx0, __shfl_xor_sync(0xffffffffu, mx0, 1));
        mx0 = fmaxf(mx0, __shfl_xor_sync(0xffffffffu, mx0, 2));
        mx1 = fmaxf(mx1, __shfl_xor_sync(0xffffffffu, mx1, 1));
        mx1 = fmaxf(mx1, __shfl_xor_sync(0xffffffffu, mx1, 2));

        const float mn0 = fmaxf(m0, mx0);
        const float mn1 = fmaxf(m1, mx1);
        const float al0 = ex2((m0 - mn0) * cs);
        const float al1 = ex2((m1 - mn1) * cs);
        m0 = mn0; m1 = mn1;

        float rs0 = 0.f, rs1 = 0.f;
        #pragma unroll
        for (int nf = 0; nf < 4; nf++) {
            s[nf][0] = ex2((s[nf][0] - mn0) * cs);
            s[nf][1] = ex2((s[nf][1] - mn0) * cs);
            s[nf][2] = ex2((s[nf][2] - mn1) * cs);
            s[nf][3] = ex2((s[nf][3] - mn1) * cs);
            rs0 += s[nf][0] + s[nf][1];
            rs1 += s[nf][2] + s[nf][3];
        }
        rs0 += __shfl_xor_sync(0xffffffffu, rs0, 1);
        rs0 += __shfl_xor_sync(0xffffffffu, rs0, 2);
        rs1 += __shfl_xor_sync(0xffffffffu, rs1, 1);
        rs1 += __shfl_xor_sync(0xffffffffu, rs1, 2);
        l0 = l0 * al0 + rs0;
        l1 = l1 * al1 + rs1;

        #pragma unroll
        for (int nf = 0; nf < 16; nf++) {
            o[nf][0] *= al0; o[nf][1] *= al0;
            o[nf][2] *= al1; o[nf][3] *= al1;
        }

        {
            float* p0 = Ps + (wm + qr) * LDP;
            float* p1 = Ps + (wm + qr + 8) * LDP;
            #pragma unroll
            for (int nf = 0; nf < 4; nf++) {
                const int c = nf * 8 + 2 * qk;
                p0[c]     = tf32r(s[nf][0]);
                p0[c + 1] = tf32r(s[nf][1]);
                p1[c]     = tf32r(s[nf][2]);
                p1[c + 1] = tf32r(s[nf][3]);
            }
        }
        __syncwarp();

        #pragma unroll
        for (int ks = 0; ks < 4; ks++) {
            unsigned a[4];
            a[0] = fb(Ps[(wm + qr) * LDP + ks * 8 + qk]);
            a[1] = fb(Ps[(wm + qr + 8) * LDP + ks * 8 + qk]);
            a[2] = fb(Ps[(wm + qr) * LDP + ks * 8 + qk + 4]);
            a[3] = fb(Ps[(wm + qr + 8) * LDP + ks * 8 + qk + 4]);
            #pragma unroll
            for (int nf = 0; nf < 16; nf++) {
                unsigned b[2];
                const int rw = (ks * 8 + qk) * LDV + nf * 8 + qr;
                b[0] = fb(Vs[rw]);
                b[1] = fb(Vs[rw + 4 * LDV]);
                mma_tf32(o[nf], a, b);
            }
        }

        __syncthreads();
        if (jt + 2 < njt) load_kv32(sbase, jt & 1, jt + 2, h, tid, Kg, Vg);
    }

    // epilogue: normalize, round to tf32 (attn feeds raw-mma stage3), store
    const float il0 = 1.f / l0;
    const float il1 = 1.f / l1;
    const int rg0 = qt * 128 + wm + qr;
    #pragma unroll
    for (int nf = 0; nf < 16; nf++) {
        const int c = h * 128 + nf * 8 + 2 * qk;
        float2 v0 = make_float2(tf32r(o[nf][0] * il0), tf32r(o[nf][1] * il0));
        float2 v1 = make_float2(tf32r(o[nf][2] * il1), tf32r(o[nf][3] * il1));
        *(float2*)(Og + (size_t)rg0 * 2048 + c)       = v0;
        *(float2*)(Og + (size_t)(rg0 + 8) * 2048 + c) = v1;
    }
}

// ---------------- launch ----------------
extern "C" void kernel_launch(void* const* d_in, const int* in_sizes, int n_in,
                              void* d_out, int out_size)
{
    const float* hs       = (const float*)d_in[0];
    const float* Wq_down  = (const float*)d_in[2];
    const float* Wq_up    = (const float*)d_in[3];
    const float* Wkv_down = (const float*)d_in[4];
    const float* Wk_up    = (const float*)d_in[5];
    const float* Wv_up    = (const float*)d_in[6];
    const float* Wo       = (const float*)d_in[7];
    float* out = (float*)d_out;

    float *q1, *q, *ckv, *k, *v, *attn;
    cudaGetSymbolAddress((void**)&q1,   g_q1);
    cudaGetSymbolAddress((void**)&q,    g_q);
    cudaGetSymbolAddress((void**)&ckv,  g_ckv);
    cudaGetSymbolAddress((void**)&k,    g_k);
    cudaGetSymbolAddress((void**)&v,    g_v);
    cudaGetSymbolAddress((void**)&attn, g_attn);

    static bool attr_set = false;
    if (!attr_set) {
        cudaFuncSetAttribute(flash_attn,
                             cudaFuncAttributeMaxDynamicSharedMemorySize, FLASH_SMEM);
        cudaFuncSetAttribute(gemm_stage1,
                             cudaFuncAttributeMaxDynamicSharedMemorySize, GEMM_SMEM);
        cudaFuncSetAttribute(gemm_stage2,
                             cudaFuncAttributeMaxDynamicSharedMemorySize, GEMM_SMEM);
        cudaFuncSetAttribute(gemm_stage3,
                             cudaFuncAttributeMaxDynamicSharedMemorySize, GEMM_SMEM);
        attr_set = true;
    }

    prep_kernel<<<19456, dim3(32, 8)>>>(hs, Wq_down, Wq_up, Wkv_down, Wk_up, Wv_up, Wo);
    gemm_stage1<<<256, 256, GEMM_SMEM>>>(q1, ckv);
    gemm_stage2<<<1024, 256, GEMM_SMEM>>>(q1, q, ckv, k, v);
    rope_kernel<<<dim3(4096, 2), 256>>>(q, k);
    flash_attn<<<dim3(NH, SEQ / 128), 256, FLASH_SMEM>>>(q, k, v, attn);
    gemm_stage3<<<256, 256, GEMM_SMEM>>>(attn, out);
}

// round 15
// speedup vs baseline: 2.4076x; 1.0031x over previous
#include <cuda_runtime.h>
#include <math.h>
#include <stdint.h>

#define SEQ 2048
#define NH 16
#define DQK 192

// ---------------- scratch (no allocations allowed) ----------------
__device__ __align__(16) float g_hs  [SEQ * 2048];
__device__ __align__(16) float g_q1  [SEQ * 1536];
__device__ __align__(16) float g_q   [SEQ * 3072];
__device__ __align__(16) float g_ckv [SEQ * 512];
__device__ __align__(16) float g_k   [SEQ * 3072];
__device__ __align__(16) float g_v   [SEQ * 2048];
__device__ __align__(16) float g_attn[SEQ * 2048];
// transposed + tf32-rounded weights [n][k]
__device__ __align__(16) float g_Tqd [1536 * 2048];
__device__ __align__(16) float g_Tqu [3072 * 1536];
__device__ __align__(16) float g_Tkvd[512 * 2048];
__device__ __align__(16) float g_Tku [3072 * 512];
__device__ __align__(16) float g_Tvu [2048 * 512];
__device__ __align__(16) float g_Two [2048 * 2048];

__device__ __forceinline__ float tf32r(float x) {
    unsigned u;
    asm("cvt.rna.tf32.f32 %0, %1;" : "=r"(u) : "f"(x));
    return __uint_as_float(u);
}
__device__ __forceinline__ unsigned fb(float x) { return __float_as_uint(x); }

__device__ __forceinline__ float ex2(float x) {
    float y;
    asm("ex2.approx.ftz.f32 %0, %1;" : "=f"(y) : "f"(x));
    return y;
}

__device__ __forceinline__ void mma_tf32(float* c, const unsigned* a, const unsigned* b) {
    asm("mma.sync.aligned.m16n8k8.row.col.f32.tf32.tf32.f32 "
        "{%0,%1,%2,%3}, {%4,%5,%6,%7}, {%8,%9}, {%0,%1,%2,%3};"
        : "+f"(c[0]), "+f"(c[1]), "+f"(c[2]), "+f"(c[3])
        : "r"(a[0]), "r"(a[1]), "r"(a[2]), "r"(a[3]), "r"(b[0]), "r"(b[1]));
}

__device__ __forceinline__ void cp16(uint32_t dst, const float* src) {
    asm volatile("cp.async.cg.shared.global [%0], [%1], 16;"
                 :: "r"(dst), "l"(__cvta_generic_to_global(src)));
}

// ---------------- prep: transpose+round weights, round-copy hs ----------------
__global__ void prep_kernel(
    const float* __restrict__ hs,
    const float* __restrict__ Wqd, const float* __restrict__ Wqu,
    const float* __restrict__ Wkvd, const float* __restrict__ Wku,
    const float* __restrict__ Wvu, const float* __restrict__ Wo)
{
    __shared__ float tl[32][33];
    int b = blockIdx.x;
    const float* in; float* out; int K, N, t; bool trans = true;
    if      (b < 3072)  { in = Wqd;  out = g_Tqd;  K = 2048; N = 1536; t = b; }
    else if (b < 7680)  { in = Wqu;  out = g_Tqu;  K = 1536; N = 3072; t = b - 3072; }
    else if (b < 8704)  { in = Wkvd; out = g_Tkvd; K = 2048; N = 512;  t = b - 7680; }
    else if (b < 10240) { in = Wku;  out = g_Tku;  K = 512;  N = 3072; t = b - 8704; }
    else if (b < 11264) { in = Wvu;  out = g_Tvu;  K = 512;  N = 2048; t = b - 10240; }
    else if (b < 15360) { in = Wo;   out = g_Two;  K = 2048; N = 2048; t = b - 11264; }
    else                { in = hs;   out = g_hs;   K = 2048; N = 2048; t = b - 15360; trans = false; }

    const int ntn = N >> 5;
    const int k0 = (t / ntn) << 5;
    const int n0 = (t % ntn) << 5;
    const int tx = threadIdx.x;
    #pragma unroll
    for (int i = 0; i < 4; i++) {
        int ty = threadIdx.y * 4 + i;
        tl[ty][tx] = in[(size_t)(k0 + ty) * N + n0 + tx];
    }
    __syncthreads();
    #pragma unroll
    for (int i = 0; i < 4; i++) {
        int ty = threadIdx.y * 4 + i;
        if (trans) out[(size_t)(n0 + ty) * K + k0 + tx] = tf32r(tl[tx][ty]);
        else       out[(size_t)(k0 + ty) * N + n0 + tx] = tf32r(tl[ty][tx]);
    }
}

// ---------------- gemm v2: NT, cp.async 4-stage, 128x128 tile, BK=16 ----------------
#define GLD 20
#define GSTG (128 * GLD)
#define GEMM_SMEM (8 * GSTG * 4)     // 81920 bytes

__device__ __forceinline__ void gemm2_core(
    const float* __restrict__ A, const float* __restrict__ Bt, float* __restrict__ C,
    int K, int lda, int ldb, int ldc, int m0, int n0, bool rnd,
    float* sa, float* sb)
{
    const int t = threadIdx.x;
    const int lane = t & 31, warp = t >> 5;
    const int wm = (warp >> 2) * 64, wn = (warp & 3) * 32;
    const int qk = lane & 3, qr = lane >> 2;
    const uint32_t sa_u = (uint32_t)__cvta_generic_to_shared(sa);
    const uint32_t sb_u = (uint32_t)__cvta_generic_to_shared(sb);

    const int nt = K >> 4;

    #define G2_ISSUE(stg, kt)                                                        \
        do {                                                                         \
            _Pragma("unroll")                                                        \
            for (int i = 0; i < 2; i++) {                                            \
                int idx = t + i * 256;                                               \
                int row = idx >> 2, kc = (idx & 3) << 2;                             \
                cp16(sa_u + ((stg) * GSTG + row * GLD + kc) * 4,                     \
                     A + (size_t)(m0 + row) * lda + (kt) + kc);                      \
                cp16(sb_u + ((stg) * GSTG + row * GLD + kc) * 4,                     \
                     Bt + (size_t)(n0 + row) * ldb + (kt) + kc);                     \
            }                                                                        \
            asm volatile("cp.async.commit_group;");                                  \
        } while (0)

    G2_ISSUE(0, 0);
    G2_ISSUE(1, 16);
    G2_ISSUE(2, 32);

    float acc[4][4][4] = {};

    for (int tt = 0; tt < nt; tt++) {
        const int rem = nt - 1 - tt;
        if (rem >= 2)      asm volatile("cp.async.wait_group 2;");
        else if (rem == 1) asm volatile("cp.async.wait_group 1;");
        else               asm volatile("cp.async.wait_group 0;");
        __syncthreads();

        if (tt + 3 < nt) G2_ISSUE((tt + 3) & 3, (tt + 3) << 4);

        const float* at = sa + (tt & 3) * GSTG;
        const float* bt = sb + (tt & 3) * GSTG;

        #pragma unroll
        for (int k8 = 0; k8 < 16; k8 += 8) {
            unsigned af[4][4], bf[4][2];
            #pragma unroll
            for (int mi = 0; mi < 4; mi++) {
                const float* r0 = at + (wm + mi * 16 + qr) * GLD + k8;
                af[mi][0] = fb(r0[qk]);
                af[mi][1] = fb(r0[8 * GLD + qk]);
                af[mi][2] = fb(r0[qk + 4]);
                af[mi][3] = fb(r0[8 * GLD + qk + 4]);
            }
            #pragma unroll
            for (int ni = 0; ni < 4; ni++) {
                const float* rn = bt + (wn + ni * 8 + qr) * GLD + k8;
                bf[ni][0] = fb(rn[qk]);
                bf[ni][1] = fb(rn[qk + 4]);
            }
            #pragma unroll
            for (int mi = 0; mi < 4; mi++)
                #pragma unroll
                for (int ni = 0; ni < 4; ni++)
                    mma_tf32(acc[mi][ni], af[mi], bf[ni]);
        }
    }

    #pragma unroll
    for (int mi = 0; mi < 4; mi++) {
        #pragma unroll
        for (int ni = 0; ni < 4; ni++) {
            const int m = m0 + wm + mi * 16 + qr;
            const int n = n0 + wn + ni * 8 + 2 * qk;
            float2 v0, v1;
            if (rnd) {
                v0.x = tf32r(acc[mi][ni][0]); v0.y = tf32r(acc[mi][ni][1]);
                v1.x = tf32r(acc[mi][ni][2]); v1.y = tf32r(acc[mi][ni][3]);
            } else {
                v0.x = acc[mi][ni][0]; v0.y = acc[mi][ni][1];
                v1.x = acc[mi][ni][2]; v1.y = acc[mi][ni][3];
            }
            *(float2*)(C + (size_t)m * ldc + n)       = v0;
            *(float2*)(C + (size_t)(m + 8) * ldc + n) = v1;
        }
    }
    #undef G2_ISSUE
}

// stage 1: hs_r @ [Wq_down | Wkv_down]^T  (256 CTAs)
__global__ __launch_bounds__(256, 2) void gemm_stage1(float* __restrict__ q1, float* __restrict__ ckv)
{
    extern __shared__ float sm2[];
    const int bid = blockIdx.x;
    const int m0 = (bid >> 4) * 128;
    const int nt = bid & 15;
    if (nt < 12)
        gemm2_core(g_hs, g_Tqd, q1, 2048, 2048, 2048, 1536, m0, nt * 128, true, sm2, sm2 + 4 * GSTG);
    else
        gemm2_core(g_hs, g_Tkvd, ckv, 2048, 2048, 2048, 512, m0, (nt - 12) * 128, true, sm2, sm2 + 4 * GSTG);
}

// stage 2: q1@Wq_up^T | ckv@Wk_up^T | ckv@Wv_up^T  (1024 CTAs)
__global__ __launch_bounds__(256, 2) void gemm_stage2(
    const float* __restrict__ q1, float* __restrict__ q,
    const float* __restrict__ ckv, float* __restrict__ k, float* __restrict__ v)
{
    extern __shared__ float sm2[];
    const int bid = blockIdx.x;
    if (bid < 384) {
        gemm2_core(q1, g_Tqu, q, 1536, 1536, 1536, 3072,
                   (bid / 24) * 128, (bid % 24) * 128, true, sm2, sm2 + 4 * GSTG);
    } else if (bid < 768) {
        const int b = bid - 384;
        gemm2_core(ckv, g_Tku, k, 512, 512, 512, 3072,
                   (b / 24) * 128, (b % 24) * 128, true, sm2, sm2 + 4 * GSTG);
    } else {
        const int b = bid - 768;
        gemm2_core(ckv, g_Tvu, v, 512, 512, 512, 2048,
                   (b / 16) * 128, (b % 16) * 128, true, sm2, sm2 + 4 * GSTG);
    }
}

// stage 3: attn @ Wo^T  (256 CTAs)
__global__ __launch_bounds__(256, 2) void gemm_stage3(
    const float* __restrict__ attn, float* __restrict__ out)
{
    extern __shared__ float sm2[];
    const int bid = blockIdx.x;
    gemm2_core(attn, g_Two, out, 2048, 2048, 2048, 2048,
               (bid >> 4) * 128, (bid & 15) * 128, false, sm2, sm2 + 4 * GSTG);
}

// ---------------- RoPE (q and k in one launch; outputs tf32-rounded) ----------------
__global__ void rope_kernel(float* __restrict__ Q, float* __restrict__ K)
{
    float* X = blockIdx.y ? K : Q;
    int idx = blockIdx.x * blockDim.x + threadIdx.x;   // SEQ*NH*32 total
    int j = idx & 31;
    int h = (idx >> 5) & (NH - 1);
    int t = idx >> 9;
    float* p = X + (size_t)t * 3072 + h * DQK + 128;
    float inv = powf(10000.0f, -(float)j / 32.0f);
    float ang = (float)t * inv;
    float s, c;
    sincosf(ang, &s, &c);
    float x1 = p[j], x2 = p[j + 32];
    p[j]      = tf32r(x1 * c - x2 * s);
    p[j + 32] = tf32r(x2 * c + x1 * s);
}

// ---------------- fused causal flash attention (v4) ----------------
// Per CTA: one head, 64 Q rows, 4 warps (128 threads), 2 CTAs/SM.
// K/V single-buffered per CTA (cross-CTA overlap hides load latency);
// K and V are separate commit groups: S-phase starts when K lands (wait 1),
// PV waits for V (wait 0).
#define LDQ 196
#define LDK 196
#define LDV 136
#define LDP 36
#define KT  32
#define QROWS 64
#define OFF_K0 (QROWS * LDQ)               // 12544
#define KBUF   (KT * LDK)                  // 6272
#define OFF_V0 (OFF_K0 + KBUF)             // 18816
#define VBUF   (KT * LDV)                  // 4352
#define OFF_P  (OFF_V0 + VBUF)             // 23168
#define FLASH_SMEM ((OFF_P + QROWS * LDP) * 4)   // 101888 bytes -> 2 CTAs/SM

__global__ __launch_bounds__(128, 2) void flash_attn(
    const float* __restrict__ Qg, const float* __restrict__ Kg,
    const float* __restrict__ Vg, float* __restrict__ Og)
{
    extern __shared__ float sm[];
    const uint32_t sbase = (uint32_t)__cvta_generic_to_shared(sm);
    float* Qs = sm;

    const int h   = blockIdx.x;
    const int qt  = 31 - blockIdx.y;      // long CTAs first
    const int tid = threadIdx.x;
    const int lane = tid & 31;
    const int warp = tid >> 5;            // 0..3
    const int qr = lane >> 2;
    const int qk = lane & 3;
    const int wm = warp * 16;

    const float cs = 0.10411758f;         // log2(e)/sqrt(192)

    // ---- load Q tile [64 x 192] (pre-rounded tf32 from producers) ----
    #pragma unroll
    for (int i = 0; i < 24; i++) {
        int idx = tid + i * 128;          // 3072 float4 chunks (48/row)
        int r = idx / 48, c = idx - r * 48;
        float4 v4 = *(const float4*)(Qg + (size_t)(qt * QROWS + r) * 3072 + h * DQK + c * 4);
        *(float4*)(Qs + r * LDQ + c * 4) = v4;
    }

    float o[16][4];
    #pragma unroll
    for (int i = 0; i < 16; i++)
        #pragma unroll
        for (int j = 0; j < 4; j++) o[i][j] = 0.f;
    float m0 = -1e30f, m1 = -1e30f, l0 = 0.f, l1 = 0.f;

    const float* Qr0 = Qs + (wm + qr) * LDQ;
    const float* Qr1 = Qs + (wm + qr + 8) * LDQ;
    const float* Ks = sm + OFF_K0;
    const float* Vs = sm + OFF_V0;
    float* Ps = sm + OFF_P;

    const int njt = 2 * qt + 2;
    for (int jt = 0; jt < njt; jt++) {
        __syncthreads();   // previous tile fully consumed (and Q visible on jt==0)

        // ---- issue K (group 1), V (group 2) ----
        {
            uint32_t kdst = sbase + OFF_K0 * 4;
            const float* ksrc = Kg + (size_t)(jt * KT) * 3072 + h * DQK;
            #pragma unroll
            for (int i = 0; i < 12; i++) {
                int idx = tid + i * 128;   // 1536 chunks (48/row)
                int r = idx / 48, c = idx - r * 48;
                cp16(kdst + (r * LDK + c * 4) * 4, ksrc + (size_t)r * 3072 + c * 4);
            }
            asm volatile("cp.async.commit_group;");
            uint32_t vdst = sbase + OFF_V0 * 4;
            const float* vsrc = Vg + (size_t)(jt * KT) * 2048 + h * 128;
            #pragma unroll
            for (int i = 0; i < 8; i++) {
                int idx = tid + i * 128;   // 1024 chunks (32/row)
                int r = idx >> 5, c = idx & 31;
                cp16(vdst + (r * LDV + c * 4) * 4, vsrc + (size_t)r * 2048 + c * 4);
            }
            asm volatile("cp.async.commit_group;");
        }

        asm volatile("cp.async.wait_group 1;");   // K ready (V may be in flight)
        __syncthreads();

        // ---- S = Q K^T : warp rows [wm, wm+16), cols [0,32) ----
        float s[4][4];
        #pragma unroll
        for (int i = 0; i < 4; i++)
            #pragma unroll
            for (int j = 0; j < 4; j++) s[i][j] = 0.f;

        #pragma unroll
        for (int ks = 0; ks < 24; ks++) {
            unsigned a[4];
            a[0] = fb(Qr0[ks * 8 + qk]);
            a[1] = fb(Qr1[ks * 8 + qk]);
            a[2] = fb(Qr0[ks * 8 + qk + 4]);
            a[3] = fb(Qr1[ks * 8 + qk + 4]);
            #pragma unroll
            for (int nf = 0; nf < 4; nf++) {
                unsigned b[2];
                const int row = (nf * 8 + qr) * LDK + ks * 8 + qk;
                b[0] = fb(Ks[row]);
                b[1] = fb(Ks[row + 4]);
                mma_tf32(s[nf], a, b);
            }
        }

        // ---- causal mask (last two tiles cross the diagonal) ----
        const int rg0 = qt * QROWS + wm + qr;
        if (jt >= 2 * qt) {
            #pragma unroll
            for (int nf = 0; nf < 4; nf++) {
                const int cg = jt * KT + nf * 8 + 2 * qk;
                if (cg     > rg0)     s[nf][0] = -1e30f;
                if (cg + 1 > rg0)     s[nf][1] = -1e30f;
                if (cg     > rg0 + 8) s[nf][2] = -1e30f;
                if (cg + 1 > rg0 + 8) s[nf][3] = -1e30f;
            }
        }

        // ---- online softmax ----
        float mx0 = -1e30f, mx1 = -1e30f;
        #pragma unroll
        for (int nf = 0; nf < 4; nf++) {
            mx0 = fmaxf(mx0, fmaxf(s[nf][0], s[nf][1]));
            mx1 = fmaxf(mx1, fmaxf(s[nf][2], s[nf][3]));
        }
        mx0 = fmaxf(mx0, __shfl_xor_sync(0xffffffffu, mx0, 1));
        mx0 = fmaxf(mx0, __shfl_xor_sync(0xffffffffu, mx0, 2));
        mx1 = fmaxf(mx1, __shfl_xor_sync(0xffffffffu, mx1, 1));
        mx1 = fmaxf(mx1, __shfl_xor_sync(0xffffffffu, mx1, 2));

        const float mn0 = fmaxf(m0, mx0);
        const float mn1 = fmaxf(m1, mx1);
        const float al0 = ex2((m0 - mn0) * cs);
        const float al1 = ex2((m1 - mn1) * cs);
        m0 = mn0; m1 = mn1;

        float rs0 = 0.f, rs1 = 0.f;
        #pragma unroll
        for (int nf = 0; nf < 4; nf++) {
            s[nf][0] = ex2((s[nf][0] - mn0) * cs);
            s[nf][1] = ex2((s[nf][1] - mn0) * cs);
            s[nf][2] = ex2((s[nf][2] - mn1) * cs);
            s[nf][3] = ex2((s[nf][3] - mn1) * cs);
            rs0 += s[nf][0] + s[nf][1];
            rs1 += s[nf][2] + s[nf][3];
        }
        rs0 += __shfl_xor_sync(0xffffffffu, rs0, 1);
        rs0 += __shfl_xor_sync(0xffffffffu, rs0, 2);
        rs1 += __shfl_xor_sync(0xffffffffu, rs1, 1);
        rs1 += __shfl_xor_sync(0xffffffffu, rs1, 2);
        l0 = l0 * al0 + rs0;
        l1 = l1 * al1 + rs1;

        #pragma unroll
        for (int nf = 0; nf < 16; nf++) {
            o[nf][0] *= al0; o[nf][1] *= al0;
            o[nf][2] *= al1; o[nf][3] *= al1;
        }

        // ---- write P (warp-private rows, tf32-rounded) ----
        {
            float* p0 = Ps + (wm + qr) * LDP;
            float* p1 = Ps + (wm + qr + 8) * LDP;
            #pragma unroll
            for (int nf = 0; nf < 4; nf++) {
                const int c = nf * 8 + 2 * qk;
                p0[c]     = tf32r(s[nf][0]);
                p0[c + 1] = tf32r(s[nf][1]);
                p1[c]     = tf32r(s[nf][2]);
                p1[c + 1] = tf32r(s[nf][3]);
            }
        }
        __syncwarp();

        asm volatile("cp.async.wait_group 0;");   // V landed
        __syncthreads();                          // V visible to all threads

        // ---- PV ----
        #pragma unroll
        for (int ks = 0; ks < 4; ks++) {
            unsigned a[4];
            a[0] = fb(Ps[(wm + qr) * LDP + ks * 8 + qk]);
            a[1] = fb(Ps[(wm + qr + 8) * LDP + ks * 8 + qk]);
            a[2] = fb(Ps[(wm + qr) * LDP + ks * 8 + qk + 4]);
            a[3] = fb(Ps[(wm + qr + 8) * LDP + ks * 8 + qk + 4]);
            #pragma unroll
            for (int nf = 0; nf < 16; nf++) {
                unsigned b[2];
                const int rw = (ks * 8 + qk) * LDV + nf * 8 + qr;
                b[0] = fb(Vs[rw]);
                b[1] = fb(Vs[rw + 4 * LDV]);
                mma_tf32(o[nf], a, b);
            }
        }
    }

    // ---- epilogue: normalize, round to tf32 (attn feeds raw-mma stage3), store ----
    const float il0 = 1.f / l0;
    const float il1 = 1.f / l1;
    const int rg0 = qt * QROWS + wm + qr;
    #pragma unroll
    for (int nf = 0; nf < 16; nf++) {
        const int c = h * 128 + nf * 8 + 2 * qk;
        float2 v0 = make_float2(tf32r(o[nf][0] * il0), tf32r(o[nf][1] * il0));
        float2 v1 = make_float2(tf32r(o[nf][2] * il1), tf32r(o[nf][3] * il1));
        *(float2*)(Og + (size_t)rg0 * 2048 + c)       = v0;
        *(float2*)(Og + (size_t)(rg0 + 8) * 2048 + c) = v1;
    }
}

// ---------------- launch ----------------
extern "C" void kernel_launch(void* const* d_in, const int* in_sizes, int n_in,
                              void* d_out, int out_size)
{
    const float* hs       = (const float*)d_in[0];
    const float* Wq_down  = (const float*)d_in[2];
    const float* Wq_up    = (const float*)d_in[3];
    const float* Wkv_down = (const float*)d_in[4];
    const float* Wk_up    = (const float*)d_in[5];
    const float* Wv_up    = (const float*)d_in[6];
    const float* Wo       = (const float*)d_in[7];
    float* out = (float*)d_out;

    float *q1, *q, *ckv, *k, *v, *attn;
    cudaGetSymbolAddress((void**)&q1,   g_q1);
    cudaGetSymbolAddress((void**)&q,    g_q);
    cudaGetSymbolAddress((void**)&ckv,  g_ckv);
    cudaGetSymbolAddress((void**)&k,    g_k);
    cudaGetSymbolAddress((void**)&v,    g_v);
    cudaGetSymbolAddress((void**)&attn, g_attn);

    static bool attr_set = false;
    if (!attr_set) {
        cudaFuncSetAttribute(flash_attn,
                             cudaFuncAttributeMaxDynamicSharedMemorySize, FLASH_SMEM);
        cudaFuncSetAttribute(gemm_stage1,
                             cudaFuncAttributeMaxDynamicSharedMemorySize, GEMM_SMEM);
        cudaFuncSetAttribute(gemm_stage2,
                             cudaFuncAttributeMaxDynamicSharedMemorySize, GEMM_SMEM);
        cudaFuncSetAttribute(gemm_stage3,
                             cudaFuncAttributeMaxDynamicSharedMemorySize, GEMM_SMEM);
        attr_set = true;
    }

    prep_kernel<<<19456, dim3(32, 8)>>>(hs, Wq_down, Wq_up, Wkv_down, Wk_up, Wv_up, Wo);
    gemm_stage1<<<256, 256, GEMM_SMEM>>>(q1, ckv);
    gemm_stage2<<<1024, 256, GEMM_SMEM>>>(q1, q, ckv, k, v);
    rope_kernel<<<dim3(4096, 2), 256>>>(q, k);
    flash_attn<<<dim3(NH, 32), 128, FLASH_SMEM>>>(q, k, v, attn);
    gemm_stage3<<<256, 256, GEMM_SMEM>>>(attn, out);
}

// round 16
// speedup vs baseline: 2.8056x; 1.1653x over previous
#include <cuda_runtime.h>
#include <math.h>
#include <stdint.h>

#define SEQ 2048
#define NH 16
#define DQK 192

// ---------------- scratch (no allocations allowed) ----------------
__device__ __align__(16) float g_hs  [SEQ * 2048];
__device__ __align__(16) float g_q1  [SEQ * 1536];
__device__ __align__(16) float g_q   [SEQ * 3072];
__device__ __align__(16) float g_ckv [SEQ * 512];
__device__ __align__(16) float g_k   [SEQ * 3072];
__device__ __align__(16) float g_v   [SEQ * 2048];
__device__ __align__(16) float g_attn[SEQ * 2048];
// transposed + tf32-rounded + k-permuted weights [n][k]
__device__ __align__(16) float g_Tqd [1536 * 2048];
__device__ __align__(16) float g_Tqu [3072 * 1536];
__device__ __align__(16) float g_Tkvd[512 * 2048];
__device__ __align__(16) float g_Tku [3072 * 512];
__device__ __align__(16) float g_Tvu [2048 * 512];
__device__ __align__(16) float g_Two [2048 * 2048];

__device__ __forceinline__ float tf32r(float x) {
    unsigned u;
    asm("cvt.rna.tf32.f32 %0, %1;" : "=r"(u) : "f"(x));
    return __uint_as_float(u);
}
__device__ __forceinline__ unsigned fb(float x) { return __float_as_uint(x); }

__device__ __forceinline__ float ex2(float x) {
    float y;
    asm("ex2.approx.ftz.f32 %0, %1;" : "=f"(y) : "f"(x));
    return y;
}

// physical position of logical index l under the 8-block k-interleave:
// within each 8-block: l<4 -> 2l ; l>=4 -> 2(l-4)+1
__device__ __forceinline__ int p8i(int l) {
    int ll = l & 7;
    return (l & ~7) | ((ll < 4) ? (ll << 1) : (((ll - 4) << 1) | 1));
}

__device__ __forceinline__ void mma_tf32(float* c, const unsigned* a, const unsigned* b) {
    asm("mma.sync.aligned.m16n8k8.row.col.f32.tf32.tf32.f32 "
        "{%0,%1,%2,%3}, {%4,%5,%6,%7}, {%8,%9}, {%0,%1,%2,%3};"
        : "+f"(c[0]), "+f"(c[1]), "+f"(c[2]), "+f"(c[3])
        : "r"(a[0]), "r"(a[1]), "r"(a[2]), "r"(a[3]), "r"(b[0]), "r"(b[1]));
}

__device__ __forceinline__ void cp16(uint32_t dst, const float* src) {
    asm volatile("cp.async.cg.shared.global [%0], [%1], 16;"
                 :: "r"(dst), "l"(__cvta_generic_to_global(src)));
}

// ---------------- prep: transpose+round+k-permute weights, round+permute hs ----------------
__global__ void prep_kernel(
    const float* __restrict__ hs,
    const float* __restrict__ Wqd, const float* __restrict__ Wqu,
    const float* __restrict__ Wkvd, const float* __restrict__ Wku,
    const float* __restrict__ Wvu, const float* __restrict__ Wo)
{
    __shared__ float tl[32][33];
    int b = blockIdx.x;
    const float* in; float* out; int K, N, t; bool trans = true;
    if      (b < 3072)  { in = Wqd;  out = g_Tqd;  K = 2048; N = 1536; t = b; }
    else if (b < 7680)  { in = Wqu;  out = g_Tqu;  K = 1536; N = 3072; t = b - 3072; }
    else if (b < 8704)  { in = Wkvd; out = g_Tkvd; K = 2048; N = 512;  t = b - 7680; }
    else if (b < 10240) { in = Wku;  out = g_Tku;  K = 512;  N = 3072; t = b - 8704; }
    else if (b < 11264) { in = Wvu;  out = g_Tvu;  K = 512;  N = 2048; t = b - 10240; }
    else if (b < 15360) { in = Wo;   out = g_Two;  K = 2048; N = 2048; t = b - 11264; }
    else                { in = hs;   out = g_hs;   K = 2048; N = 2048; t = b - 15360; trans = false; }

    const int ntn = N >> 5;
    const int k0 = (t / ntn) << 5;
    const int n0 = (t % ntn) << 5;
    const int tx = threadIdx.x;
    #pragma unroll
    for (int i = 0; i < 4; i++) {
        int ty = threadIdx.y * 4 + i;
        tl[ty][tx] = in[(size_t)(k0 + ty) * N + n0 + tx];
    }
    __syncthreads();
    #pragma unroll
    for (int i = 0; i < 4; i++) {
        int ty = threadIdx.y * 4 + i;
        if (trans) out[(size_t)(n0 + ty) * K + p8i(k0 + tx)] = tf32r(tl[tx][ty]);
        else       out[(size_t)(k0 + ty) * N + p8i(n0 + tx)] = tf32r(tl[ty][tx]);
    }
}

// ---------------- gemm v3: NT, cp.async 2-stage, 128x128 tile, BK=32, k-permuted ----------------
#define GLD 40
#define GSTG (128 * GLD)             // 5120 floats per stage per operand
#define GEMM_SMEM (4 * GSTG * 4)     // 81920 bytes (2 stages x 2 operands)

__device__ __forceinline__ void gemm2_core(
    const float* __restrict__ A, const float* __restrict__ Bt, float* __restrict__ C,
    int K, int lda, int ldb, int ldc, int m0, int n0, bool permN,
    float* sa, float* sb)
{
    const int t = threadIdx.x;
    const int lane = t & 31, warp = t >> 5;
    const int wm = (warp >> 2) * 64, wn = (warp & 3) * 32;
    const int qk = lane & 3, qr = lane >> 2;
    const uint32_t sa_u = (uint32_t)__cvta_generic_to_shared(sa);
    const uint32_t sb_u = (uint32_t)__cvta_generic_to_shared(sb);

    const int nt = K >> 5;

    #define G2_ISSUE(stg, kt)                                                        \
        do {                                                                         \
            _Pragma("unroll")                                                        \
            for (int i = 0; i < 4; i++) {                                            \
                int idx = t + i * 256;                                               \
                int row = idx >> 3, kc = (idx & 7) << 2;                             \
                cp16(sa_u + ((stg) * GSTG + row * GLD + kc) * 4,                     \
                     A + (size_t)(m0 + row) * lda + (kt) + kc);                      \
                cp16(sb_u + ((stg) * GSTG + row * GLD + kc) * 4,                     \
                     Bt + (size_t)(n0 + row) * ldb + (kt) + kc);                     \
            }                                                                        \
            asm volatile("cp.async.commit_group;");                                  \
        } while (0)

    G2_ISSUE(0, 0);

    float acc[4][4][4] = {};

    for (int tt = 0; tt < nt; tt++) {
        asm volatile("cp.async.wait_group 0;");
        __syncthreads();
        if (tt + 1 < nt) G2_ISSUE((tt + 1) & 1, (tt + 1) << 5);

        const float* at = sa + (tt & 1) * GSTG;
        const float* bt = sb + (tt & 1) * GSTG;

        #pragma unroll
        for (int k8 = 0; k8 < 32; k8 += 8) {
            unsigned af[4][4], bf[4][2];
            #pragma unroll
            for (int mi = 0; mi < 4; mi++) {
                const float* r0 = at + (wm + mi * 16 + qr) * GLD + k8 + 2 * qk;
                float2 lo = *(const float2*)r0;                 // logical (qk, qk+4)
                float2 hi = *(const float2*)(r0 + 8 * GLD);
                af[mi][0] = fb(lo.x); af[mi][2] = fb(lo.y);
                af[mi][1] = fb(hi.x); af[mi][3] = fb(hi.y);
            }
            #pragma unroll
            for (int ni = 0; ni < 4; ni++) {
                float2 bb = *(const float2*)(bt + (wn + ni * 8 + qr) * GLD + k8 + 2 * qk);
                bf[ni][0] = fb(bb.x); bf[ni][1] = fb(bb.y);
            }
            #pragma unroll
            for (int mi = 0; mi < 4; mi++)
                #pragma unroll
                for (int ni = 0; ni < 4; ni++)
                    mma_tf32(acc[mi][ni], af[mi], bf[ni]);
        }
    }

    #pragma unroll
    for (int mi = 0; mi < 4; mi++) {
        #pragma unroll
        for (int ni = 0; ni < 4; ni++) {
            const int m = m0 + wm + mi * 16 + qr;
            if (permN) {
                // logical cols (2qk, 2qk+1) -> physical (base, base+2)
                const int base = n0 + wn + ni * 8 + ((qk < 2) ? 4 * qk : 4 * qk - 7);
                C[(size_t)m * ldc + base]           = tf32r(acc[mi][ni][0]);
                C[(size_t)m * ldc + base + 2]       = tf32r(acc[mi][ni][1]);
                C[(size_t)(m + 8) * ldc + base]     = tf32r(acc[mi][ni][2]);
                C[(size_t)(m + 8) * ldc + base + 2] = tf32r(acc[mi][ni][3]);
            } else {
                const int n = n0 + wn + ni * 8 + 2 * qk;
                float2 v0 = make_float2(acc[mi][ni][0], acc[mi][ni][1]);
                float2 v1 = make_float2(acc[mi][ni][2], acc[mi][ni][3]);
                *(float2*)(C + (size_t)m * ldc + n)       = v0;
                *(float2*)(C + (size_t)(m + 8) * ldc + n) = v1;
            }
        }
    }
    #undef G2_ISSUE
}

// stage 1: hs_r @ [Wq_down | Wkv_down]^T  (256 CTAs)
__global__ __launch_bounds__(256, 2) void gemm_stage1(float* __restrict__ q1, float* __restrict__ ckv)
{
    extern __shared__ float sm2[];
    const int bid = blockIdx.x;
    const int m0 = (bid >> 4) * 128;
    const int nt = bid & 15;
    if (nt < 12)
        gemm2_core(g_hs, g_Tqd, q1, 2048, 2048, 2048, 1536, m0, nt * 128, true, sm2, sm2 + 2 * GSTG);
    else
        gemm2_core(g_hs, g_Tkvd, ckv, 2048, 2048, 2048, 512, m0, (nt - 12) * 128, true, sm2, sm2 + 2 * GSTG);
}

// stage 2: q1@Wq_up^T | ckv@Wk_up^T | ckv@Wv_up^T  (1024 CTAs)
__global__ __launch_bounds__(256, 2) void gemm_stage2(
    const float* __restrict__ q1, float* __restrict__ q,
    const float* __restrict__ ckv, float* __restrict__ k, float* __restrict__ v)
{
    extern __shared__ float sm2[];
    const int bid = blockIdx.x;
    if (bid < 384) {
        gemm2_core(q1, g_Tqu, q, 1536, 1536, 1536, 3072,
                   (bid / 24) * 128, (bid % 24) * 128, true, sm2, sm2 + 2 * GSTG);
    } else if (bid < 768) {
        const int b = bid - 384;
        gemm2_core(ckv, g_Tku, k, 512, 512, 512, 3072,
                   (b / 24) * 128, (b % 24) * 128, true, sm2, sm2 + 2 * GSTG);
    } else {
        const int b = bid - 768;
        gemm2_core(ckv, g_Tvu, v, 512, 512, 512, 2048,
                   (b / 16) * 128, (b % 16) * 128, true, sm2, sm2 + 2 * GSTG);
    }
}

// stage 3: attn @ Wo^T  (256 CTAs) — final output, NOT permuted
__global__ __launch_bounds__(256, 2) void gemm_stage3(
    const float* __restrict__ attn, float* __restrict__ out)
{
    extern __shared__ float sm2[];
    const int bid = blockIdx.x;
    gemm2_core(attn, g_Two, out, 2048, 2048, 2048, 2048,
               (bid >> 4) * 128, (bid & 15) * 128, false, sm2, sm2 + 2 * GSTG);
}

// ---------------- RoPE (permutation-aware; outputs tf32-rounded) ----------------
__global__ void rope_kernel(float* __restrict__ Q, float* __restrict__ K)
{
    float* X = blockIdx.y ? K : Q;
    int idx = blockIdx.x * blockDim.x + threadIdx.x;   // SEQ*NH*32 total
    int j = idx & 31;                                  // logical rope pair index
    int h = (idx >> 5) & (NH - 1);
    int t = idx >> 9;
    float* p = X + (size_t)t * 3072 + h * DQK + 128;
    float inv = powf(10000.0f, -(float)j / 32.0f);
    float ang = (float)t * inv;
    float s, c;
    sincosf(ang, &s, &c);
    const int pj1 = p8i(j);        // physical slot of logical j
    const int pj2 = p8i(j + 32);   // physical slot of logical j+32
    float x1 = p[pj1], x2 = p[pj2];
    p[pj1] = tf32r(x1 * c - x2 * s);
    p[pj2] = tf32r(x2 * c + x1 * s);
}

// ---------------- fused causal flash attention (v5: k-permuted float2 frags) ----------------
#define LDQ 200
#define LDK 200
#define LDV 136
#define LDP 36
#define KT  32
#define QROWS 64
#define OFF_K0 (QROWS * LDQ)               // 12800
#define KBUF   (KT * LDK)                  // 6400
#define OFF_V0 (OFF_K0 + KBUF)             // 19200
#define VBUF   (KT * LDV)                  // 4352
#define OFF_P  (OFF_V0 + VBUF)             // 23552
#define FLASH_SMEM ((OFF_P + QROWS * LDP) * 4)   // 103424 bytes -> 2 CTAs/SM

__global__ __launch_bounds__(128, 2) void flash_attn(
    const float* __restrict__ Qg, const float* __restrict__ Kg,
    const float* __restrict__ Vg, float* __restrict__ Og)
{
    extern __shared__ float sm[];
    const uint32_t sbase = (uint32_t)__cvta_generic_to_shared(sm);
    float* Qs = sm;

    const int h   = blockIdx.x;
    const int qt  = 31 - blockIdx.y;      // long CTAs first
    const int tid = threadIdx.x;
    const int lane = tid & 31;
    const int warp = tid >> 5;            // 0..3
    const int qr = lane >> 2;
    const int qk = lane & 3;
    const int wm = warp * 16;

    const float cs = 0.10411758f;         // log2(e)/sqrt(192)

    // ---- load Q tile [64 x 192] (pre-rounded tf32, k-permuted layout) ----
    #pragma unroll
    for (int i = 0; i < 24; i++) {
        int idx = tid + i * 128;          // 3072 float4 chunks (48/row)
        int r = idx / 48, c = idx - r * 48;
        float4 v4 = *(const float4*)(Qg + (size_t)(qt * QROWS + r) * 3072 + h * DQK + c * 4);
        *(float4*)(Qs + r * LDQ + c * 4) = v4;
    }

    float o[16][4];
    #pragma unroll
    for (int i = 0; i < 16; i++)
        #pragma unroll
        for (int j = 0; j < 4; j++) o[i][j] = 0.f;
    float m0 = -1e30f, m1 = -1e30f, l0 = 0.f, l1 = 0.f;

    const float* Qr0 = Qs + (wm + qr) * LDQ;
    const float* Qr1 = Qs + (wm + qr + 8) * LDQ;
    const float* Ks = sm + OFF_K0;
    const float* Vs = sm + OFF_V0;
    float* Ps = sm + OFF_P;

    const int njt = 2 * qt + 2;
    for (int jt = 0; jt < njt; jt++) {
        __syncthreads();   // previous tile fully consumed (and Q visible on jt==0)

        // ---- issue K (group 1), V (group 2) ----
        {
            uint32_t kdst = sbase + OFF_K0 * 4;
            const float* ksrc = Kg + (size_t)(jt * KT) * 3072 + h * DQK;
            #pragma unroll
            for (int i = 0; i < 12; i++) {
                int idx = tid + i * 128;   // 1536 chunks (48/row)
                int r = idx / 48, c = idx - r * 48;
                cp16(kdst + (r * LDK + c * 4) * 4, ksrc + (size_t)r * 3072 + c * 4);
            }
            asm volatile("cp.async.commit_group;");
            uint32_t vdst = sbase + OFF_V0 * 4;
            const float* vsrc = Vg + (size_t)(jt * KT) * 2048 + h * 128;
            #pragma unroll
            for (int i = 0; i < 8; i++) {
                int idx = tid + i * 128;   // 1024 chunks (32/row)
                int r = idx >> 5, c = idx & 31;
                cp16(vdst + (r * LDV + c * 4) * 4, vsrc + (size_t)r * 2048 + c * 4);
            }
            asm volatile("cp.async.commit_group;");
        }

        asm volatile("cp.async.wait_group 1;");   // K ready (V may be in flight)
        __syncthreads();

        // ---- S = Q K^T (float2 fragment loads: logical pair (qk, qk+4)) ----
        float s[4][4];
        #pragma unroll
        for (int i = 0; i < 4; i++)
            #pragma unroll
            for (int j = 0; j < 4; j++) s[i][j] = 0.f;

        #pragma unroll
        for (int ks = 0; ks < 24; ks++) {
            float2 qa0 = *(const float2*)(Qr0 + ks * 8 + 2 * qk);
            float2 qa1 = *(const float2*)(Qr1 + ks * 8 + 2 * qk);
            unsigned a[4];
            a[0] = fb(qa0.x); a[1] = fb(qa1.x);
            a[2] = fb(qa0.y); a[3] = fb(qa1.y);
            #pragma unroll
            for (int nf = 0; nf < 4; nf++) {
                float2 kb = *(const float2*)(Ks + (nf * 8 + qr) * LDK + ks * 8 + 2 * qk);
                unsigned b[2] = { fb(kb.x), fb(kb.y) };
                mma_tf32(s[nf], a, b);
            }
        }

        // ---- causal mask (key positions = K rows, unpermuted) ----
        const int rg0 = qt * QROWS + wm + qr;
        if (jt >= 2 * qt) {
            #pragma unroll
            for (int nf = 0; nf < 4; nf++) {
                const int cg = jt * KT + nf * 8 + 2 * qk;
                if (cg     > rg0)     s[nf][0] = -1e30f;
                if (cg + 1 > rg0)     s[nf][1] = -1e30f;
                if (cg     > rg0 + 8) s[nf][2] = -1e30f;
                if (cg + 1 > rg0 + 8) s[nf][3] = -1e30f;
            }
        }

        // ---- online softmax ----
        float mx0 = -1e30f, mx1 = -1e30f;
        #pragma unroll
        for (int nf = 0; nf < 4; nf++) {
            mx0 = fmaxf(mx0, fmaxf(s[nf][0], s[nf][1]));
            mx1 = fmaxf(mx1, fmaxf(s[nf][2], s[nf][3]));
        }
        mx0 = fmaxf(mx0, __shfl_xor_sync(0xffffffffu, mx0, 1));
        mx0 = fmaxf(mx0, __shfl_xor_sync(0xffffffffu, mx0, 2));
        mx1 = fmaxf(mx1, __shfl_xor_sync(0xffffffffu, mx1, 1));
        mx1 = fmaxf(mx1, __shfl_xor_sync(0xffffffffu, mx1, 2));

        const float mn0 = fmaxf(m0, mx0);
        const float mn1 = fmaxf(m1, mx1);
        const float al0 = ex2((m0 - mn0) * cs);
        const float al1 = ex2((m1 - mn1) * cs);
        m0 = mn0; m1 = mn1;

        float rs0 = 0.f, rs1 = 0.f;
        #pragma unroll
        for (int nf = 0; nf < 4; nf++) {
            s[nf][0] = ex2((s[nf][0] - mn0) * cs);
            s[nf][1] = ex2((s[nf][1] - mn0) * cs);
            s[nf][2] = ex2((s[nf][2] - mn1) * cs);
            s[nf][3] = ex2((s[nf][3] - mn1) * cs);
            rs0 += s[nf][0] + s[nf][1];
            rs1 += s[nf][2] + s[nf][3];
        }
        rs0 += __shfl_xor_sync(0xffffffffu, rs0, 1);
        rs0 += __shfl_xor_sync(0xffffffffu, rs0, 2);
        rs1 += __shfl_xor_sync(0xffffffffu, rs1, 1);
        rs1 += __shfl_xor_sync(0xffffffffu, rs1, 2);
        l0 = l0 * al0 + rs0;
        l1 = l1 * al1 + rs1;

        #pragma unroll
        for (int nf = 0; nf < 16; nf++) {
            o[nf][0] *= al0; o[nf][1] *= al0;
            o[nf][2] *= al1; o[nf][3] *= al1;
        }

        // ---- write P (key positions unpermuted; tf32-rounded) ----
        {
            float* p0 = Ps + (wm + qr) * LDP;
            float* p1 = Ps + (wm + qr + 8) * LDP;
            #pragma unroll
            for (int nf = 0; nf < 4; nf++) {
                const int c = nf * 8 + 2 * qk;
                p0[c]     = tf32r(s[nf][0]);
                p0[c + 1] = tf32r(s[nf][1]);
                p1[c]     = tf32r(s[nf][2]);
                p1[c + 1] = tf32r(s[nf][3]);
            }
        }
        __syncwarp();

        asm volatile("cp.async.wait_group 0;");   // V landed
        __syncthreads();

        // ---- PV (V columns physical = permuted head dims; pure relabel) ----
        #pragma unroll
        for (int ks = 0; ks < 4; ks++) {
            unsigned a[4];
            a[0] = fb(Ps[(wm + qr) * LDP + ks * 8 + qk]);
            a[1] = fb(Ps[(wm + qr + 8) * LDP + ks * 8 + qk]);
            a[2] = fb(Ps[(wm + qr) * LDP + ks * 8 + qk + 4]);
            a[3] = fb(Ps[(wm + qr + 8) * LDP + ks * 8 + qk + 4]);
            #pragma unroll
            for (int nf = 0; nf < 16; nf++) {
                unsigned b[2];
                const int rw = (ks * 8 + qk) * LDV + nf * 8 + qr;
                b[0] = fb(Vs[rw]);
                b[1] = fb(Vs[rw + 4 * LDV]);
                mma_tf32(o[nf], a, b);
            }
        }
    }

    // ---- epilogue: attn stored in physical (V-permuted) column layout ----
    const float il0 = 1.f / l0;
    const float il1 = 1.f / l1;
    const int rg0 = qt * QROWS + wm + qr;
    #pragma unroll
    for (int nf = 0; nf < 16; nf++) {
        const int c = h * 128 + nf * 8 + 2 * qk;
        float2 v0 = make_float2(tf32r(o[nf][0] * il0), tf32r(o[nf][1] * il0));
        float2 v1 = make_float2(tf32r(o[nf][2] * il1), tf32r(o[nf][3] * il1));
        *(float2*)(Og + (size_t)rg0 * 2048 + c)       = v0;
        *(float2*)(Og + (size_t)(rg0 + 8) * 2048 + c) = v1;
    }
}

// ---------------- launch ----------------
extern "C" void kernel_launch(void* const* d_in, const int* in_sizes, int n_in,
                              void* d_out, int out_size)
{
    const float* hs       = (const float*)d_in[0];
    const float* Wq_down  = (const float*)d_in[2];
    const float* Wq_up    = (const float*)d_in[3];
    const float* Wkv_down = (const float*)d_in[4];
    const float* Wk_up    = (const float*)d_in[5];
    const float* Wv_up    = (const float*)d_in[6];
    const float* Wo       = (const float*)d_in[7];
    float* out = (float*)d_out;

    float *q1, *q, *ckv, *k, *v, *attn;
    cudaGetSymbolAddress((void**)&q1,   g_q1);
    cudaGetSymbolAddress((void**)&q,    g_q);
    cudaGetSymbolAddress((void**)&ckv,  g_ckv);
    cudaGetSymbolAddress((void**)&k,    g_k);
    cudaGetSymbolAddress((void**)&v,    g_v);
    cudaGetSymbolAddress((void**)&attn, g_attn);

    static bool attr_set = false;
    if (!attr_set) {
        cudaFuncSetAttribute(flash_attn,
                             cudaFuncAttributeMaxDynamicSharedMemorySize, FLASH_SMEM);
        cudaFuncSetAttribute(gemm_stage1,
                             cudaFuncAttributeMaxDynamicSharedMemorySize, GEMM_SMEM);
        cudaFuncSetAttribute(gemm_stage2,
                             cudaFuncAttributeMaxDynamicSharedMemorySize, GEMM_SMEM);
        cudaFuncSetAttribute(gemm_stage3,
                             cudaFuncAttributeMaxDynamicSharedMemorySize, GEMM_SMEM);
        attr_set = true;
    }

    prep_kernel<<<19456, dim3(32, 8)>>>(hs, Wq_down, Wq_up, Wkv_down, Wk_up, Wv_up, Wo);
    gemm_stage1<<<256, 256, GEMM_SMEM>>>(q1, ckv);
    gemm_stage2<<<1024, 256, GEMM_SMEM>>>(q1, q, ckv, k, v);
    rope_kernel<<<dim3(4096, 2), 256>>>(q, k);
    flash_attn<<<dim3(NH, 32), 128, FLASH_SMEM>>>(q, k, v, attn);
    gemm_stage3<<<256, 256, GEMM_SMEM>>>(attn, out);
}